// round 2
// baseline (speedup 1.0000x reference)
#include <cuda_runtime.h>
#include <math.h>

#define TOK 18432
#define SCALE 0.35355339059327373f

static __device__ float g_X [TOK*512];
static __device__ float g_Y [TOK*1536];
static __device__ float g_A [TOK*512];
static __device__ float g_P [TOK*512];
static __device__ float g_x1[TOK*512];
static __device__ float g_sts[32*32*2];
static __device__ float g_stt[1152*32*2];

// ---------------- spatial GN stats: per (bt, group) over 16ch x 576 ----------------
__global__ void gn_stats_s(const float* __restrict__ x) {
    int bt = blockIdx.x, g = blockIdx.y;
    int b = bt >> 4, t = bt & 15;
    const float* base = x + ((size_t)(b*512 + g*16))*9216 + (size_t)t*576;
    float s = 0.f, ss = 0.f;
    for (int e = threadIdx.x; e < 9216; e += 256) {
        int cc = e / 576, hw = e - cc*576;
        float v = base[(size_t)cc*9216 + hw];
        s += v; ss += v*v;
    }
    __shared__ float rs[8], rss[8];
    #pragma unroll
    for (int o = 16; o; o >>= 1) {
        s  += __shfl_xor_sync(0xffffffffu, s,  o);
        ss += __shfl_xor_sync(0xffffffffu, ss, o);
    }
    int w = threadIdx.x >> 5;
    if ((threadIdx.x & 31) == 0) { rs[w] = s; rss[w] = ss; }
    __syncthreads();
    if (threadIdx.x == 0) {
        s = 0.f; ss = 0.f;
        #pragma unroll
        for (int i = 0; i < 8; i++) { s += rs[i]; ss += rss[i]; }
        float mean = s * (1.f/9216.f);
        float var  = ss * (1.f/9216.f) - mean*mean;
        g_sts[(bt*32+g)*2+0] = mean;
        g_sts[(bt*32+g)*2+1] = rsqrtf(var + 1e-5f);
    }
}

// --------- normalize + transpose spatial: x(natural) -> g_X[(bt*576+hw)*512+c] ---------
__global__ void norm_tr_s(const float* __restrict__ x,
                          const float* __restrict__ gw, const float* __restrict__ gb) {
    __shared__ float tile[32][33];
    int bt = blockIdx.x, b = bt >> 4, t = bt & 15;
    int hw0 = blockIdx.y*32, c0 = blockIdx.z*32;
    int tx = threadIdx.x, ty = threadIdx.y;
    #pragma unroll
    for (int i = 0; i < 4; i++) {
        int cl = ty + i*8, c = c0 + cl;
        float mean = g_sts[(bt*32 + (c>>4))*2+0];
        float rstd = g_sts[(bt*32 + (c>>4))*2+1];
        float v = x[(((size_t)b*512 + c)*16 + t)*576 + hw0 + tx];
        tile[cl][tx] = (v - mean)*rstd*gw[c] + gb[c];
    }
    __syncthreads();
    #pragma unroll
    for (int i = 0; i < 4; i++) {
        int hwl = ty + i*8;
        g_X[((size_t)(bt*576 + hw0 + hwl))*512 + c0 + tx] = tile[tx][hwl];
    }
}

// ---------------- SGEMM NT: C[M,N] = A[M,K] @ W[N,K]^T + bias ----------------
__global__ __launch_bounds__(256) void sgemm_nt(
    const float* __restrict__ A, const float* __restrict__ W,
    const float* __restrict__ bias, float* __restrict__ C, int M, int N, int K) {
    __shared__ __align__(16) float As[16][128];
    __shared__ __align__(16) float Bs[16][128];
    int tid = threadIdx.x, tr = tid >> 4, tc = tid & 15;
    const float* Ag = A + (size_t)blockIdx.y*128*K;
    const float* Wg = W + (size_t)blockIdx.x*128*K;
    float acc[8][8];
    #pragma unroll
    for (int i = 0; i < 8; i++)
        #pragma unroll
        for (int j = 0; j < 8; j++) acc[i][j] = 0.f;
    for (int k0 = 0; k0 < K; k0 += 16) {
        #pragma unroll
        for (int s = 0; s < 2; s++) {
            int id = tid + s*256, r = id >> 2, c4 = (id & 3) << 2;
            float4 av = *(const float4*)(Ag + (size_t)r*K + k0 + c4);
            As[c4+0][r] = av.x; As[c4+1][r] = av.y; As[c4+2][r] = av.z; As[c4+3][r] = av.w;
            float4 bv = *(const float4*)(Wg + (size_t)r*K + k0 + c4);
            Bs[c4+0][r] = bv.x; Bs[c4+1][r] = bv.y; Bs[c4+2][r] = bv.z; Bs[c4+3][r] = bv.w;
        }
        __syncthreads();
        #pragma unroll
        for (int k = 0; k < 16; k++) {
            float ra[8], rb[8];
            *(float4*)&ra[0] = *(const float4*)&As[k][tr*4];
            *(float4*)&ra[4] = *(const float4*)&As[k][64 + tr*4];
            *(float4*)&rb[0] = *(const float4*)&Bs[k][tc*4];
            *(float4*)&rb[4] = *(const float4*)&Bs[k][64 + tc*4];
            #pragma unroll
            for (int i = 0; i < 8; i++)
                #pragma unroll
                for (int j = 0; j < 8; j++) acc[i][j] += ra[i]*rb[j];
        }
        __syncthreads();
    }
    #pragma unroll
    for (int i = 0; i < 8; i++) {
        int row = blockIdx.y*128 + ((i < 4) ? (tr*4 + i) : (64 + tr*4 + i - 4));
        #pragma unroll
        for (int jj = 0; jj < 2; jj++) {
            int col = blockIdx.x*128 + tc*4 + jj*64;
            float4 o;
            o.x = acc[i][jj*4+0] + bias[col+0];
            o.y = acc[i][jj*4+1] + bias[col+1];
            o.z = acc[i][jj*4+2] + bias[col+2];
            o.w = acc[i][jj*4+3] + bias[col+3];
            *(float4*)(C + (size_t)row*N + col) = o;
        }
    }
}

// ---------------- spatial flash attention: grid (9 qtiles, 8 heads, 32 ns) ----------------
__global__ __launch_bounds__(256) void attn_spatial(const float* __restrict__ Y,
                                                    float* __restrict__ O) {
    extern __shared__ float sm[];
    float* qs = sm;            // [64][68]
    float* ks = sm + 64*68;
    float* vs = sm + 2*64*68;
    float* ps = sm + 3*64*68;
    int q0 = blockIdx.x*64, h = blockIdx.y, ns = blockIdx.z;
    int tid = threadIdx.x, ty = tid >> 4, tx = tid & 15;
    {   // load Q, fold 1/8 scale
        int r = tid >> 2, d0 = (tid & 3)*16;
        const float* src = Y + ((size_t)(ns*576 + q0 + r))*1536 + h*64 + d0;
        #pragma unroll
        for (int j = 0; j < 4; j++) {
            float4 v = *(const float4*)(src + j*4);
            qs[r*68 + d0 + j*4 + 0] = v.x*0.125f; qs[r*68 + d0 + j*4 + 1] = v.y*0.125f;
            qs[r*68 + d0 + j*4 + 2] = v.z*0.125f; qs[r*68 + d0 + j*4 + 3] = v.w*0.125f;
        }
    }
    float acc[4][4], m[4], l[4];
    #pragma unroll
    for (int i = 0; i < 4; i++) {
        m[i] = -1e30f; l[i] = 0.f;
        #pragma unroll
        for (int j = 0; j < 4; j++) acc[i][j] = 0.f;
    }
    for (int ch = 0; ch < 9; ch++) {
        __syncthreads();
        {   // load K, V chunk
            int r = tid >> 2, d0 = (tid & 3)*16;
            const float* ksrc = Y + ((size_t)(ns*576 + ch*64 + r))*1536 + 512 + h*64 + d0;
            #pragma unroll
            for (int j = 0; j < 4; j++) {
                float4 kv = *(const float4*)(ksrc + j*4);
                ks[r*68 + d0 + j*4 + 0] = kv.x; ks[r*68 + d0 + j*4 + 1] = kv.y;
                ks[r*68 + d0 + j*4 + 2] = kv.z; ks[r*68 + d0 + j*4 + 3] = kv.w;
                float4 vv = *(const float4*)(ksrc + 512 + j*4);
                vs[r*68 + d0 + j*4 + 0] = vv.x; vs[r*68 + d0 + j*4 + 1] = vv.y;
                vs[r*68 + d0 + j*4 + 2] = vv.z; vs[r*68 + d0 + j*4 + 3] = vv.w;
            }
        }
        __syncthreads();
        float sv[4][4];
        #pragma unroll
        for (int i = 0; i < 4; i++)
            #pragma unroll
            for (int j = 0; j < 4; j++) sv[i][j] = 0.f;
        for (int d = 0; d < 64; d += 4) {
            float4 qv[4], kv[4];
            #pragma unroll
            for (int i = 0; i < 4; i++) qv[i] = *(const float4*)&qs[(4*ty+i)*68 + d];
            #pragma unroll
            for (int j = 0; j < 4; j++) kv[j] = *(const float4*)&ks[(tx+16*j)*68 + d];
            #pragma unroll
            for (int i = 0; i < 4; i++)
                #pragma unroll
                for (int j = 0; j < 4; j++)
                    sv[i][j] += qv[i].x*kv[j].x + qv[i].y*kv[j].y + qv[i].z*kv[j].z + qv[i].w*kv[j].w;
        }
        #pragma unroll
        for (int i = 0; i < 4; i++) {
            float mx = fmaxf(fmaxf(sv[i][0], sv[i][1]), fmaxf(sv[i][2], sv[i][3]));
            #pragma unroll
            for (int o = 8; o; o >>= 1) mx = fmaxf(mx, __shfl_xor_sync(0xffffffffu, mx, o, 16));
            float mn = fmaxf(m[i], mx);
            float al = __expf(m[i] - mn);
            float rs = 0.f;
            #pragma unroll
            for (int j = 0; j < 4; j++) {
                float p = __expf(sv[i][j] - mn);
                ps[(4*ty+i)*68 + tx + 16*j] = p;
                rs += p;
            }
            #pragma unroll
            for (int o = 8; o; o >>= 1) rs += __shfl_xor_sync(0xffffffffu, rs, o, 16);
            l[i] = l[i]*al + rs;
            m[i] = mn;
            #pragma unroll
            for (int j = 0; j < 4; j++) acc[i][j] *= al;
        }
        __syncthreads();
        for (int s = 0; s < 64; s += 4) {
            float4 pv[4], vv[4];
            #pragma unroll
            for (int i = 0; i < 4; i++) pv[i] = *(const float4*)&ps[(4*ty+i)*68 + s];
            #pragma unroll
            for (int j = 0; j < 4; j++) vv[j] = *(const float4*)&vs[(s+j)*68 + 4*tx];
            #pragma unroll
            for (int i = 0; i < 4; i++) {
                acc[i][0] += pv[i].x*vv[0].x + pv[i].y*vv[1].x + pv[i].z*vv[2].x + pv[i].w*vv[3].x;
                acc[i][1] += pv[i].x*vv[0].y + pv[i].y*vv[1].y + pv[i].z*vv[2].y + pv[i].w*vv[3].y;
                acc[i][2] += pv[i].x*vv[0].z + pv[i].y*vv[1].z + pv[i].z*vv[2].z + pv[i].w*vv[3].z;
                acc[i][3] += pv[i].x*vv[0].w + pv[i].y*vv[1].w + pv[i].z*vv[2].w + pv[i].w*vv[3].w;
            }
        }
    }
    #pragma unroll
    for (int i = 0; i < 4; i++) {
        float inv = 1.f / l[i];
        float4 o;
        o.x = acc[i][0]*inv; o.y = acc[i][1]*inv; o.z = acc[i][2]*inv; o.w = acc[i][3]*inv;
        *(float4*)(O + ((size_t)(ns*576 + q0 + 4*ty + i))*512 + h*64 + 4*tx) = o;
    }
}

// --------- spatial residual: x1 = x + transpose-back(g_P) ---------
__global__ void resid_s(const float* __restrict__ x) {
    __shared__ float tile[32][33];
    int bt = blockIdx.x, b = bt >> 4, t = bt & 15;
    int hw0 = blockIdx.y*32, c0 = blockIdx.z*32;
    int tx = threadIdx.x, ty = threadIdx.y;
    #pragma unroll
    for (int i = 0; i < 4; i++) {
        int hwl = ty + i*8;
        tile[tx][hwl] = g_P[((size_t)(bt*576 + hw0 + hwl))*512 + c0 + tx];
    }
    __syncthreads();
    #pragma unroll
    for (int i = 0; i < 4; i++) {
        int cl = ty + i*8;
        size_t idx = (((size_t)b*512 + c0 + cl)*16 + t)*576 + hw0 + tx;
        g_x1[idx] = x[idx] + tile[cl][tx];
    }
}

// ---------------- temporal GN stats: per (b,hw,group) over 16ch x 16t ----------------
__global__ void gn_stats_t() {
    int b = blockIdx.x, g = blockIdx.y, hw = threadIdx.x;
    const float* base = g_x1 + ((size_t)b*512 + g*16)*9216 + hw;
    float s = 0.f, ss = 0.f;
    for (int cc = 0; cc < 16; cc++)
        #pragma unroll
        for (int t = 0; t < 16; t++) {
            float v = base[(size_t)cc*9216 + t*576];
            s += v; ss += v*v;
        }
    float mean = s*(1.f/256.f);
    float var  = ss*(1.f/256.f) - mean*mean;
    g_stt[((size_t)(b*576+hw)*32 + g)*2 + 0] = mean;
    g_stt[((size_t)(b*576+hw)*32 + g)*2 + 1] = rsqrtf(var + 1e-5f);
}

// --------- normalize + transpose temporal: g_x1 -> g_X[((b*576+hw)*16+t)*512+c] ---------
__global__ void norm_tr_t(const float* __restrict__ gw, const float* __restrict__ gb) {
    __shared__ float tile[32][33];
    int bt = blockIdx.x, b = bt >> 4, t = bt & 15;
    int hw0 = blockIdx.y*32, c0 = blockIdx.z*32;
    int tx = threadIdx.x, ty = threadIdx.y;
    #pragma unroll
    for (int i = 0; i < 4; i++) {
        int cl = ty + i*8, c = c0 + cl, hw = hw0 + tx;
        float mean = g_stt[((size_t)(b*576+hw)*32 + (c>>4))*2 + 0];
        float rstd = g_stt[((size_t)(b*576+hw)*32 + (c>>4))*2 + 1];
        float v = g_x1[(((size_t)b*512 + c)*16 + t)*576 + hw];
        tile[cl][tx] = (v - mean)*rstd*gw[c] + gb[c];
    }
    __syncthreads();
    #pragma unroll
    for (int i = 0; i < 4; i++) {
        int hwl = ty + i*8;
        g_X[((size_t)((b*576 + hw0 + hwl)*16 + t))*512 + c0 + tx] = tile[tx][hwl];
    }
}

// ---------------- temporal attention: grid (8 heads, 1152 samples) ----------------
__global__ __launch_bounds__(256) void attn_temporal(const float* __restrict__ Y,
    const float* __restrict__ rpk, const float* __restrict__ rpv, float* __restrict__ O) {
    __shared__ float qs[16][68], ks[16][68], vs[16][68];
    __shared__ float pk[33][68], pvt[33][68], wsm[16][20];
    int h = blockIdx.x, samp = blockIdx.y, tid = threadIdx.x;
    for (int i = tid; i < 33*64; i += 256) {
        pk [i>>6][i&63] = rpk[i];
        pvt[i>>6][i&63] = rpv[i];
    }
    {
        int t = tid >> 4, d0 = (tid & 15)*4;
        const float* base = Y + ((size_t)(samp*16 + t))*1536 + h*64 + d0;
        float4 q4 = *(const float4*)(base);
        float4 k4 = *(const float4*)(base + 512);
        float4 v4 = *(const float4*)(base + 1024);
        qs[t][d0+0]=q4.x; qs[t][d0+1]=q4.y; qs[t][d0+2]=q4.z; qs[t][d0+3]=q4.w;
        ks[t][d0+0]=k4.x; ks[t][d0+1]=k4.y; ks[t][d0+2]=k4.z; ks[t][d0+3]=k4.w;
        vs[t][d0+0]=v4.x; vs[t][d0+1]=v4.y; vs[t][d0+2]=v4.z; vs[t][d0+3]=v4.w;
    }
    __syncthreads();
    {
        int t = tid >> 4, s = tid & 15;
        float wv = -1e30f;
        if (s <= t) {
            float a = 0.f, bb = 0.f;
            int ri = t - s + 16;
            for (int d = 0; d < 64; d++) {
                a  += qs[t][d]*ks[s][d];
                bb += qs[s][d]*pk[ri][d];
            }
            wv = 0.125f*a + SCALE*bb;
        }
        float mx = wv;
        #pragma unroll
        for (int o = 8; o; o >>= 1) mx = fmaxf(mx, __shfl_xor_sync(0xffffffffu, mx, o, 16));
        float e = (s <= t) ? __expf(wv - mx) : 0.f;
        float sum = e;
        #pragma unroll
        for (int o = 8; o; o >>= 1) sum += __shfl_xor_sync(0xffffffffu, sum, o, 16);
        wsm[t][s] = e / sum;
    }
    __syncthreads();
    {
        int t = tid >> 4, d0 = (tid & 15)*4;
        float o0 = 0.f, o1 = 0.f, o2 = 0.f, o3 = 0.f;
        #pragma unroll
        for (int s = 0; s < 16; s++) {
            float p = wsm[t][s];
            int ri = s - t + 16;
            o0 += p*(vs[s][d0+0] + pvt[ri][d0+0]);
            o1 += p*(vs[s][d0+1] + pvt[ri][d0+1]);
            o2 += p*(vs[s][d0+2] + pvt[ri][d0+2]);
            o3 += p*(vs[s][d0+3] + pvt[ri][d0+3]);
        }
        float4 o = {o0, o1, o2, o3};
        *(float4*)(O + ((size_t)(samp*16 + t))*512 + h*64 + d0) = o;
    }
}

// --------- final add: out = x1 + transpose-back(g_P, temporal layout) ---------
__global__ void final_add(float* __restrict__ out) {
    __shared__ float tile[32][33];
    int bt = blockIdx.x, b = bt >> 4, t = bt & 15;
    int hw0 = blockIdx.y*32, c0 = blockIdx.z*32;
    int tx = threadIdx.x, ty = threadIdx.y;
    #pragma unroll
    for (int i = 0; i < 4; i++) {
        int hwl = ty + i*8;
        tile[tx][hwl] = g_P[((size_t)((b*576 + hw0 + hwl)*16 + t))*512 + c0 + tx];
    }
    __syncthreads();
    #pragma unroll
    for (int i = 0; i < 4; i++) {
        int cl = ty + i*8;
        size_t idx = (((size_t)b*512 + c0 + cl)*16 + t)*576 + hw0 + tx;
        out[idx] = g_x1[idx] + tile[cl][tx];
    }
}

extern "C" void kernel_launch(void* const* d_in, const int* in_sizes, int n_in,
                              void* d_out, int out_size) {
    const float* x        = (const float*)d_in[0];
    const float* norm_s_w = (const float*)d_in[1];
    const float* norm_s_b = (const float*)d_in[2];
    const float* qkv_s_w  = (const float*)d_in[3];
    const float* qkv_s_b  = (const float*)d_in[4];
    const float* proj_s_w = (const float*)d_in[5];
    const float* proj_s_b = (const float*)d_in[6];
    const float* norm_t_w = (const float*)d_in[7];
    const float* norm_t_b = (const float*)d_in[8];
    const float* qkv_t_w  = (const float*)d_in[9];
    const float* qkv_t_b  = (const float*)d_in[10];
    const float* proj_t_w = (const float*)d_in[11];
    const float* proj_t_b = (const float*)d_in[12];
    const float* rpk      = (const float*)d_in[13];
    const float* rpv      = (const float*)d_in[14];
    float* out = (float*)d_out;

    float *gX, *gY, *gA, *gP;
    cudaGetSymbolAddress((void**)&gX, g_X);
    cudaGetSymbolAddress((void**)&gY, g_Y);
    cudaGetSymbolAddress((void**)&gA, g_A);
    cudaGetSymbolAddress((void**)&gP, g_P);

    cudaFuncSetAttribute(attn_spatial, cudaFuncAttributeMaxDynamicSharedMemorySize, 4*64*68*4);

    dim3 tb(32, 8);
    dim3 tg(32, 18, 16);

    // spatial branch
    gn_stats_s<<<dim3(32,32), 256>>>(x);
    norm_tr_s<<<tg, tb>>>(x, norm_s_w, norm_s_b);
    sgemm_nt<<<dim3(12,144), 256>>>(gX, qkv_s_w, qkv_s_b, gY, TOK, 1536, 512);
    attn_spatial<<<dim3(9,8,32), 256, 4*64*68*4>>>(gY, gA);
    sgemm_nt<<<dim3(4,144), 256>>>(gA, proj_s_w, proj_s_b, gP, TOK, 512, 512);
    resid_s<<<tg, tb>>>(x);

    // temporal branch
    gn_stats_t<<<dim3(2,32), 576>>>();
    norm_tr_t<<<tg, tb>>>(norm_t_w, norm_t_b);
    sgemm_nt<<<dim3(12,144), 256>>>(gX, qkv_t_w, qkv_t_b, gY, TOK, 1536, 512);
    attn_temporal<<<dim3(8,1152), 256>>>(gY, rpk, rpv, gA);
    sgemm_nt<<<dim3(4,144), 256>>>(gA, proj_t_w, proj_t_b, gP, TOK, 512, 512);
    final_add<<<tg, tb>>>(out);
}

// round 4
// speedup vs baseline: 1.5494x; 1.5494x over previous
#include <cuda_runtime.h>
#include <cuda_bf16.h>
#include <stdint.h>
#include <math.h>

#define TOK 18432
#define SCALE 0.35355339059327373f

static __device__ float g_Y [TOK*1536];
static __device__ float g_P [TOK*512];
static __device__ float g_x1[TOK*512];
static __device__ __nv_bfloat16 g_Ah[TOK*512];
static __device__ __nv_bfloat16 g_Al[TOK*512];
static __device__ __nv_bfloat16 g_Wh[1536*512];
static __device__ __nv_bfloat16 g_Wl[1536*512];
static __device__ float g_sts[32*32*2];
static __device__ float g_stt[1152*32*2];

static __device__ __forceinline__ uint32_t s2u(const void* p) {
    uint32_t a;
    asm("{ .reg .u64 t; cvta.to.shared.u64 t, %1; cvt.u32.u64 %0, t; }" : "=r"(a) : "l"(p));
    return a;
}
static __device__ __forceinline__ void ldm4(uint32_t* r, uint32_t addr) {
    asm volatile("ldmatrix.sync.aligned.m8n8.x4.shared.b16 {%0,%1,%2,%3}, [%4];"
        : "=r"(r[0]), "=r"(r[1]), "=r"(r[2]), "=r"(r[3]) : "r"(addr));
}
static __device__ __forceinline__ void mma16816(float* d, const uint32_t* a, uint32_t b0, uint32_t b1) {
    asm volatile("mma.sync.aligned.m16n8k16.row.col.f32.bf16.bf16.f32 "
        "{%0,%1,%2,%3}, {%4,%5,%6,%7}, {%8,%9}, {%0,%1,%2,%3};"
        : "+f"(d[0]), "+f"(d[1]), "+f"(d[2]), "+f"(d[3])
        : "r"(a[0]), "r"(a[1]), "r"(a[2]), "r"(a[3]), "r"(b0), "r"(b1));
}
static __device__ __forceinline__ void split2(float v, __nv_bfloat16& h, __nv_bfloat16& l) {
    h = __float2bfloat16_rn(v);
    l = __float2bfloat16_rn(v - __bfloat162float(h));
}

// ---------------- spatial GN stats ----------------
__global__ void gn_stats_s(const float* __restrict__ x) {
    int bt = blockIdx.x, g = blockIdx.y;
    int b = bt >> 4, t = bt & 15;
    const float* base = x + ((size_t)(b*512 + g*16))*9216 + (size_t)t*576;
    float s = 0.f, ss = 0.f;
    for (int e = threadIdx.x; e < 9216; e += 256) {
        int cc = e / 576, hw = e - cc*576;
        float v = base[(size_t)cc*9216 + hw];
        s += v; ss += v*v;
    }
    __shared__ float rs[8], rss[8];
    #pragma unroll
    for (int o = 16; o; o >>= 1) {
        s  += __shfl_xor_sync(0xffffffffu, s,  o);
        ss += __shfl_xor_sync(0xffffffffu, ss, o);
    }
    int w = threadIdx.x >> 5;
    if ((threadIdx.x & 31) == 0) { rs[w] = s; rss[w] = ss; }
    __syncthreads();
    if (threadIdx.x == 0) {
        s = 0.f; ss = 0.f;
        #pragma unroll
        for (int i = 0; i < 8; i++) { s += rs[i]; ss += rss[i]; }
        float mean = s * (1.f/9216.f);
        float var  = ss * (1.f/9216.f) - mean*mean;
        g_sts[(bt*32+g)*2+0] = mean;
        g_sts[(bt*32+g)*2+1] = rsqrtf(var + 1e-5f);
    }
}

// --------- normalize + transpose spatial -> hi/lo bf16 token-major ---------
__global__ void norm_tr_s(const float* __restrict__ x,
                          const float* __restrict__ gw, const float* __restrict__ gb) {
    __shared__ float tile[32][33];
    int bt = blockIdx.x, b = bt >> 4, t = bt & 15;
    int hw0 = blockIdx.y*32, c0 = blockIdx.z*32;
    int tx = threadIdx.x, ty = threadIdx.y;
    #pragma unroll
    for (int i = 0; i < 4; i++) {
        int cl = ty + i*8, c = c0 + cl;
        float mean = g_sts[(bt*32 + (c>>4))*2+0];
        float rstd = g_sts[(bt*32 + (c>>4))*2+1];
        float v = x[(((size_t)b*512 + c)*16 + t)*576 + hw0 + tx];
        tile[cl][tx] = (v - mean)*rstd*gw[c] + gb[c];
    }
    __syncthreads();
    #pragma unroll
    for (int i = 0; i < 4; i++) {
        int hwl = ty + i*8;
        size_t o = ((size_t)(bt*576 + hw0 + hwl))*512 + c0 + tx;
        __nv_bfloat16 h, l; split2(tile[tx][hwl], h, l);
        g_Ah[o] = h; g_Al[o] = l;
    }
}

// ---------------- weight split ----------------
__global__ void wsplit(const float* __restrict__ w, int n) {
    int i = blockIdx.x*256 + threadIdx.x;
    if (i < n) {
        __nv_bfloat16 h, l; split2(w[i], h, l);
        g_Wh[i] = h; g_Wl[i] = l;
    }
}

// ---------------- bf16x3 HMMA GEMM: C[M,N] = A @ W^T + bias, K=512 ----------------
// 128x128 tile, 8 warps (2m x 4n), K-chunks of 64, padded smem stride 72.
#define SPAD 72
__global__ __launch_bounds__(256) void gemm_mma(
    const __nv_bfloat16* __restrict__ Ah, const __nv_bfloat16* __restrict__ Al,
    const __nv_bfloat16* __restrict__ Bh, const __nv_bfloat16* __restrict__ Bl,
    const float* __restrict__ bias, float* __restrict__ C, int N) {
    extern __shared__ __nv_bfloat16 sm[];
    __nv_bfloat16* sAh = sm;
    __nv_bfloat16* sAl = sm + 9216;
    __nv_bfloat16* sBh = sm + 18432;
    __nv_bfloat16* sBl = sm + 27648;
    int tid = threadIdx.x, wid = tid >> 5, lane = tid & 31;
    int wm = wid >> 2, wn = wid & 3;
    int m0 = blockIdx.y*128, n0 = blockIdx.x*128;
    const __nv_bfloat16* pAh = Ah + (size_t)m0*512;
    const __nv_bfloat16* pAl = Al + (size_t)m0*512;
    const __nv_bfloat16* pBh = Bh + (size_t)n0*512;
    const __nv_bfloat16* pBl = Bl + (size_t)n0*512;

    float acc[4][4][4];
    #pragma unroll
    for (int i = 0; i < 4; i++)
        #pragma unroll
        for (int j = 0; j < 4; j++)
            #pragma unroll
            for (int k = 0; k < 4; k++) acc[i][j][k] = 0.f;

    // ldmatrix base addresses (element offsets within padded tiles)
    int lrow = lane & 15, lcol = (lane >> 4) << 3;
    uint32_t aoff = (uint32_t)(( (wm*64 + lrow) * SPAD + lcol ) * 2);
    uint32_t boff = (uint32_t)(( (wn*32 + lrow) * SPAD + lcol ) * 2);
    uint32_t uAh = s2u(sAh) + aoff, uAl = s2u(sAl) + aoff;
    uint32_t uBh = s2u(sBh) + boff, uBl = s2u(sBl) + boff;

    for (int chunk = 0; chunk < 8; chunk++) {
        int koff = chunk*64;
        __syncthreads();
        #pragma unroll
        for (int i = 0; i < 4; i++) {
            int idx = tid + i*256;
            int r = idx >> 3, c8 = (idx & 7) << 3;
            size_t go = (size_t)r*512 + koff + c8;
            int so = r*SPAD + c8;
            *(float4*)(sAh + so) = *(const float4*)(pAh + go);
            *(float4*)(sAl + so) = *(const float4*)(pAl + go);
            *(float4*)(sBh + so) = *(const float4*)(pBh + go);
            *(float4*)(sBl + so) = *(const float4*)(pBl + go);
        }
        __syncthreads();
        #pragma unroll
        for (int k16 = 0; k16 < 4; k16++) {
            uint32_t kb = k16*32;  // 16 elems * 2 bytes
            uint32_t ah[4][4], al[4][4], bh[2][4], bl[2][4];
            #pragma unroll
            for (int mi = 0; mi < 4; mi++) {
                ldm4(ah[mi], uAh + mi*16*SPAD*2 + kb);
                ldm4(al[mi], uAl + mi*16*SPAD*2 + kb);
            }
            #pragma unroll
            for (int nj = 0; nj < 2; nj++) {
                ldm4(bh[nj], uBh + nj*16*SPAD*2 + kb);
                ldm4(bl[nj], uBl + nj*16*SPAD*2 + kb);
            }
            #pragma unroll
            for (int mi = 0; mi < 4; mi++)
                #pragma unroll
                for (int ni = 0; ni < 4; ni++) {
                    int nj = ni >> 1, hf = ni & 1;
                    mma16816(acc[mi][ni], ah[mi], bh[nj][hf], bh[nj][hf+2]);
                    mma16816(acc[mi][ni], al[mi], bh[nj][hf], bh[nj][hf+2]);
                    mma16816(acc[mi][ni], ah[mi], bl[nj][hf], bl[nj][hf+2]);
                }
        }
    }
    // epilogue
    int rbase = m0 + wm*64 + (lane >> 2);
    int cbase = n0 + wn*32 + (lane & 3)*2;
    #pragma unroll
    for (int mi = 0; mi < 4; mi++)
        #pragma unroll
        for (int ni = 0; ni < 4; ni++) {
            int col = cbase + ni*8;
            float2 bv = *(const float2*)(bias + col);
            int r0 = rbase + mi*16;
            float2 o0 = { acc[mi][ni][0] + bv.x, acc[mi][ni][1] + bv.y };
            float2 o1 = { acc[mi][ni][2] + bv.x, acc[mi][ni][3] + bv.y };
            *(float2*)(C + (size_t)r0*N + col) = o0;
            *(float2*)(C + (size_t)(r0+8)*N + col) = o1;
        }
}

// ---------------- spatial flash attention ----------------
__global__ __launch_bounds__(256) void attn_spatial(const float* __restrict__ Y,
        __nv_bfloat16* __restrict__ Oh, __nv_bfloat16* __restrict__ Ol) {
    extern __shared__ float smf[];
    float* qs = smf;
    float* ks = smf + 64*68;
    float* vs = smf + 2*64*68;
    float* ps = smf + 3*64*68;
    int q0 = blockIdx.x*64, h = blockIdx.y, ns = blockIdx.z;
    int tid = threadIdx.x, ty = tid >> 4, tx = tid & 15;
    {
        int r = tid >> 2, d0 = (tid & 3)*16;
        const float* src = Y + ((size_t)(ns*576 + q0 + r))*1536 + h*64 + d0;
        #pragma unroll
        for (int j = 0; j < 4; j++) {
            float4 v = *(const float4*)(src + j*4);
            qs[r*68 + d0 + j*4 + 0] = v.x*0.125f; qs[r*68 + d0 + j*4 + 1] = v.y*0.125f;
            qs[r*68 + d0 + j*4 + 2] = v.z*0.125f; qs[r*68 + d0 + j*4 + 3] = v.w*0.125f;
        }
    }
    float acc[4][4], m[4], l[4];
    #pragma unroll
    for (int i = 0; i < 4; i++) {
        m[i] = -1e30f; l[i] = 0.f;
        #pragma unroll
        for (int j = 0; j < 4; j++) acc[i][j] = 0.f;
    }
    for (int ch = 0; ch < 9; ch++) {
        __syncthreads();
        {
            int r = tid >> 2, d0 = (tid & 3)*16;
            const float* ksrc = Y + ((size_t)(ns*576 + ch*64 + r))*1536 + 512 + h*64 + d0;
            #pragma unroll
            for (int j = 0; j < 4; j++) {
                float4 kv = *(const float4*)(ksrc + j*4);
                ks[r*68 + d0 + j*4 + 0] = kv.x; ks[r*68 + d0 + j*4 + 1] = kv.y;
                ks[r*68 + d0 + j*4 + 2] = kv.z; ks[r*68 + d0 + j*4 + 3] = kv.w;
                float4 vv = *(const float4*)(ksrc + 512 + j*4);
                vs[r*68 + d0 + j*4 + 0] = vv.x; vs[r*68 + d0 + j*4 + 1] = vv.y;
                vs[r*68 + d0 + j*4 + 2] = vv.z; vs[r*68 + d0 + j*4 + 3] = vv.w;
            }
        }
        __syncthreads();
        float sv[4][4];
        #pragma unroll
        for (int i = 0; i < 4; i++)
            #pragma unroll
            for (int j = 0; j < 4; j++) sv[i][j] = 0.f;
        for (int d = 0; d < 64; d += 4) {
            float4 qv[4], kv[4];
            #pragma unroll
            for (int i = 0; i < 4; i++) qv[i] = *(const float4*)&qs[(4*ty+i)*68 + d];
            #pragma unroll
            for (int j = 0; j < 4; j++) kv[j] = *(const float4*)&ks[(tx+16*j)*68 + d];
            #pragma unroll
            for (int i = 0; i < 4; i++)
                #pragma unroll
                for (int j = 0; j < 4; j++)
                    sv[i][j] += qv[i].x*kv[j].x + qv[i].y*kv[j].y + qv[i].z*kv[j].z + qv[i].w*kv[j].w;
        }
        #pragma unroll
        for (int i = 0; i < 4; i++) {
            float mx = fmaxf(fmaxf(sv[i][0], sv[i][1]), fmaxf(sv[i][2], sv[i][3]));
            #pragma unroll
            for (int o = 8; o; o >>= 1) mx = fmaxf(mx, __shfl_xor_sync(0xffffffffu, mx, o, 16));
            float mn = fmaxf(m[i], mx);
            float al = __expf(m[i] - mn);
            float rs = 0.f;
            #pragma unroll
            for (int j = 0; j < 4; j++) {
                float p = __expf(sv[i][j] - mn);
                ps[(4*ty+i)*68 + tx + 16*j] = p;
                rs += p;
            }
            #pragma unroll
            for (int o = 8; o; o >>= 1) rs += __shfl_xor_sync(0xffffffffu, rs, o, 16);
            l[i] = l[i]*al + rs;
            m[i] = mn;
            #pragma unroll
            for (int j = 0; j < 4; j++) acc[i][j] *= al;
        }
        __syncthreads();
        for (int s = 0; s < 64; s += 4) {
            float4 pv[4], vv[4];
            #pragma unroll
            for (int i = 0; i < 4; i++) pv[i] = *(const float4*)&ps[(4*ty+i)*68 + s];
            #pragma unroll
            for (int j = 0; j < 4; j++) vv[j] = *(const float4*)&vs[(s+j)*68 + 4*tx];
            #pragma unroll
            for (int i = 0; i < 4; i++) {
                acc[i][0] += pv[i].x*vv[0].x + pv[i].y*vv[1].x + pv[i].z*vv[2].x + pv[i].w*vv[3].x;
                acc[i][1] += pv[i].x*vv[0].y + pv[i].y*vv[1].y + pv[i].z*vv[2].y + pv[i].w*vv[3].y;
                acc[i][2] += pv[i].x*vv[0].z + pv[i].y*vv[1].z + pv[i].z*vv[2].z + pv[i].w*vv[3].z;
                acc[i][3] += pv[i].x*vv[0].w + pv[i].y*vv[1].w + pv[i].z*vv[2].w + pv[i].w*vv[3].w;
            }
        }
    }
    #pragma unroll
    for (int i = 0; i < 4; i++) {
        float inv = 1.f / l[i];
        size_t off = ((size_t)(ns*576 + q0 + 4*ty + i))*512 + h*64 + 4*tx;
        __nv_bfloat16 h0, l0, h1, l1, h2, l2, h3, l3;
        split2(acc[i][0]*inv, h0, l0); split2(acc[i][1]*inv, h1, l1);
        split2(acc[i][2]*inv, h2, l2); split2(acc[i][3]*inv, h3, l3);
        *(__nv_bfloat162*)(Oh + off)     = __halves2bfloat162(h0, h1);
        *(__nv_bfloat162*)(Oh + off + 2) = __halves2bfloat162(h2, h3);
        *(__nv_bfloat162*)(Ol + off)     = __halves2bfloat162(l0, l1);
        *(__nv_bfloat162*)(Ol + off + 2) = __halves2bfloat162(l2, l3);
    }
}

// --------- spatial residual: x1 = x + transpose-back(g_P) ---------
__global__ void resid_s(const float* __restrict__ x) {
    __shared__ float tile[32][33];
    int bt = blockIdx.x, b = bt >> 4, t = bt & 15;
    int hw0 = blockIdx.y*32, c0 = blockIdx.z*32;
    int tx = threadIdx.x, ty = threadIdx.y;
    #pragma unroll
    for (int i = 0; i < 4; i++) {
        int hwl = ty + i*8;
        tile[tx][hwl] = g_P[((size_t)(bt*576 + hw0 + hwl))*512 + c0 + tx];
    }
    __syncthreads();
    #pragma unroll
    for (int i = 0; i < 4; i++) {
        int cl = ty + i*8;
        size_t idx = (((size_t)b*512 + c0 + cl)*16 + t)*576 + hw0 + tx;
        g_x1[idx] = x[idx] + tile[cl][tx];
    }
}

// ---------------- temporal GN stats ----------------
__global__ void gn_stats_t() {
    int b = blockIdx.x, g = blockIdx.y, hw = threadIdx.x;
    const float* base = g_x1 + ((size_t)b*512 + g*16)*9216 + hw;
    float s = 0.f, ss = 0.f;
    for (int cc = 0; cc < 16; cc++)
        #pragma unroll
        for (int t = 0; t < 16; t++) {
            float v = base[(size_t)cc*9216 + t*576];
            s += v; ss += v*v;
        }
    float mean = s*(1.f/256.f);
    float var  = ss*(1.f/256.f) - mean*mean;
    g_stt[((size_t)(b*576+hw)*32 + g)*2 + 0] = mean;
    g_stt[((size_t)(b*576+hw)*32 + g)*2 + 1] = rsqrtf(var + 1e-5f);
}

// --------- normalize + transpose temporal -> hi/lo bf16 token-major ---------
__global__ void norm_tr_t(const float* __restrict__ gw, const float* __restrict__ gb) {
    __shared__ float tile[32][33];
    int bt = blockIdx.x, b = bt >> 4, t = bt & 15;
    int hw0 = blockIdx.y*32, c0 = blockIdx.z*32;
    int tx = threadIdx.x, ty = threadIdx.y;
    #pragma unroll
    for (int i = 0; i < 4; i++) {
        int cl = ty + i*8, c = c0 + cl, hw = hw0 + tx;
        float mean = g_stt[((size_t)(b*576+hw)*32 + (c>>4))*2 + 0];
        float rstd = g_stt[((size_t)(b*576+hw)*32 + (c>>4))*2 + 1];
        float v = g_x1[(((size_t)b*512 + c)*16 + t)*576 + hw];
        tile[cl][tx] = (v - mean)*rstd*gw[c] + gb[c];
    }
    __syncthreads();
    #pragma unroll
    for (int i = 0; i < 4; i++) {
        int hwl = ty + i*8;
        size_t o = ((size_t)((b*576 + hw0 + hwl)*16 + t))*512 + c0 + tx;
        __nv_bfloat16 h, l; split2(tile[tx][hwl], h, l);
        g_Ah[o] = h; g_Al[o] = l;
    }
}

// ---------------- temporal attention ----------------
__global__ __launch_bounds__(256) void attn_temporal(const float* __restrict__ Y,
    const float* __restrict__ rpk, const float* __restrict__ rpv,
    __nv_bfloat16* __restrict__ Oh, __nv_bfloat16* __restrict__ Ol) {
    __shared__ float qs[16][68], ks[16][68], vs[16][68];
    __shared__ float pk[33][68], pvt[33][68], wsm[16][20];
    int h = blockIdx.x, samp = blockIdx.y, tid = threadIdx.x;
    for (int i = tid; i < 33*64; i += 256) {
        pk [i>>6][i&63] = rpk[i];
        pvt[i>>6][i&63] = rpv[i];
    }
    {
        int t = tid >> 4, d0 = (tid & 15)*4;
        const float* base = Y + ((size_t)(samp*16 + t))*1536 + h*64 + d0;
        float4 q4 = *(const float4*)(base);
        float4 k4 = *(const float4*)(base + 512);
        float4 v4 = *(const float4*)(base + 1024);
        qs[t][d0+0]=q4.x; qs[t][d0+1]=q4.y; qs[t][d0+2]=q4.z; qs[t][d0+3]=q4.w;
        ks[t][d0+0]=k4.x; ks[t][d0+1]=k4.y; ks[t][d0+2]=k4.z; ks[t][d0+3]=k4.w;
        vs[t][d0+0]=v4.x; vs[t][d0+1]=v4.y; vs[t][d0+2]=v4.z; vs[t][d0+3]=v4.w;
    }
    __syncthreads();
    {
        int t = tid >> 4, s = tid & 15;
        float wv = -1e30f;
        if (s <= t) {
            float a = 0.f, bb = 0.f;
            int ri = t - s + 16;
            for (int d = 0; d < 64; d++) {
                a  += qs[t][d]*ks[s][d];
                bb += qs[s][d]*pk[ri][d];
            }
            wv = 0.125f*a + SCALE*bb;
        }
        float mx = wv;
        #pragma unroll
        for (int o = 8; o; o >>= 1) mx = fmaxf(mx, __shfl_xor_sync(0xffffffffu, mx, o, 16));
        float e = (s <= t) ? __expf(wv - mx) : 0.f;
        float sum = e;
        #pragma unroll
        for (int o = 8; o; o >>= 1) sum += __shfl_xor_sync(0xffffffffu, sum, o, 16);
        wsm[t][s] = e / sum;
    }
    __syncthreads();
    {
        int t = tid >> 4, d0 = (tid & 15)*4;
        float o0 = 0.f, o1 = 0.f, o2 = 0.f, o3 = 0.f;
        #pragma unroll
        for (int s = 0; s < 16; s++) {
            float p = wsm[t][s];
            int ri = s - t + 16;
            o0 += p*(vs[s][d0+0] + pvt[ri][d0+0]);
            o1 += p*(vs[s][d0+1] + pvt[ri][d0+1]);
            o2 += p*(vs[s][d0+2] + pvt[ri][d0+2]);
            o3 += p*(vs[s][d0+3] + pvt[ri][d0+3]);
        }
        size_t off = ((size_t)(samp*16 + t))*512 + h*64 + d0;
        __nv_bfloat16 h0, l0, h1, l1, h2, l2, h3, l3;
        split2(o0, h0, l0); split2(o1, h1, l1);
        split2(o2, h2, l2); split2(o3, h3, l3);
        *(__nv_bfloat162*)(Oh + off)     = __halves2bfloat162(h0, h1);
        *(__nv_bfloat162*)(Oh + off + 2) = __halves2bfloat162(h2, h3);
        *(__nv_bfloat162*)(Ol + off)     = __halves2bfloat162(l0, l1);
        *(__nv_bfloat162*)(Ol + off + 2) = __halves2bfloat162(l2, l3);
    }
}

// --------- final add ---------
__global__ void final_add(float* __restrict__ out) {
    __shared__ float tile[32][33];
    int bt = blockIdx.x, b = bt >> 4, t = bt & 15;
    int hw0 = blockIdx.y*32, c0 = blockIdx.z*32;
    int tx = threadIdx.x, ty = threadIdx.y;
    #pragma unroll
    for (int i = 0; i < 4; i++) {
        int hwl = ty + i*8;
        tile[tx][hwl] = g_P[((size_t)((b*576 + hw0 + hwl)*16 + t))*512 + c0 + tx];
    }
    __syncthreads();
    #pragma unroll
    for (int i = 0; i < 4; i++) {
        int cl = ty + i*8;
        size_t idx = (((size_t)b*512 + c0 + cl)*16 + t)*576 + hw0 + tx;
        out[idx] = g_x1[idx] + tile[cl][tx];
    }
}

extern "C" void kernel_launch(void* const* d_in, const int* in_sizes, int n_in,
                              void* d_out, int out_size) {
    const float* x        = (const float*)d_in[0];
    const float* norm_s_w = (const float*)d_in[1];
    const float* norm_s_b = (const float*)d_in[2];
    const float* qkv_s_w  = (const float*)d_in[3];
    const float* qkv_s_b  = (const float*)d_in[4];
    const float* proj_s_w = (const float*)d_in[5];
    const float* proj_s_b = (const float*)d_in[6];
    const float* norm_t_w = (const float*)d_in[7];
    const float* norm_t_b = (const float*)d_in[8];
    const float* qkv_t_w  = (const float*)d_in[9];
    const float* qkv_t_b  = (const float*)d_in[10];
    const float* proj_t_w = (const float*)d_in[11];
    const float* proj_t_b = (const float*)d_in[12];
    const float* rpk      = (const float*)d_in[13];
    const float* rpv      = (const float*)d_in[14];
    float* out = (float*)d_out;

    float *gY, *gP;
    __nv_bfloat16 *gAh, *gAl, *gWh, *gWl;
    cudaGetSymbolAddress((void**)&gY,  g_Y);
    cudaGetSymbolAddress((void**)&gP,  g_P);
    cudaGetSymbolAddress((void**)&gAh, g_Ah);
    cudaGetSymbolAddress((void**)&gAl, g_Al);
    cudaGetSymbolAddress((void**)&gWh, g_Wh);
    cudaGetSymbolAddress((void**)&gWl, g_Wl);

    const int GEMM_SMEM = 36864 * 2;  // 4 tiles of 128x72 bf16
    cudaFuncSetAttribute(attn_spatial, cudaFuncAttributeMaxDynamicSharedMemorySize, 4*64*68*4);
    cudaFuncSetAttribute(gemm_mma, cudaFuncAttributeMaxDynamicSharedMemorySize, GEMM_SMEM);

    dim3 tb(32, 8);
    dim3 tg(32, 18, 16);

    // spatial branch
    gn_stats_s<<<dim3(32,32), 256>>>(x);
    norm_tr_s<<<tg, tb>>>(x, norm_s_w, norm_s_b);
    wsplit<<<3072, 256>>>(qkv_s_w, 1536*512);
    gemm_mma<<<dim3(12,144), 256, GEMM_SMEM>>>(gAh, gAl, gWh, gWl, qkv_s_b, gY, 1536);
    attn_spatial<<<dim3(9,8,32), 256, 4*64*68*4>>>(gY, gAh, gAl);
    wsplit<<<1024, 256>>>(proj_s_w, 512*512);
    gemm_mma<<<dim3(4,144), 256, GEMM_SMEM>>>(gAh, gAl, gWh, gWl, proj_s_b, gP, 512);
    resid_s<<<tg, tb>>>(x);

    // temporal branch
    gn_stats_t<<<dim3(2,32), 576>>>();
    norm_tr_t<<<tg, tb>>>(norm_t_w, norm_t_b);
    wsplit<<<3072, 256>>>(qkv_t_w, 1536*512);
    gemm_mma<<<dim3(12,144), 256, GEMM_SMEM>>>(gAh, gAl, gWh, gWl, qkv_t_b, gY, 1536);
    attn_temporal<<<dim3(8,1152), 256>>>(gY, rpk, rpv, gAh, gAl);
    wsplit<<<1024, 256>>>(proj_t_w, 512*512);
    gemm_mma<<<dim3(4,144), 256, GEMM_SMEM>>>(gAh, gAl, gWh, gWl, proj_t_b, gP, 512);
    final_add<<<tg, tb>>>(out);
}

// round 5
// speedup vs baseline: 1.7098x; 1.1035x over previous
#include <cuda_runtime.h>
#include <cuda_bf16.h>
#include <stdint.h>
#include <math.h>

#define TOK 18432
#define SCALE 0.35355339059327373f

static __device__ float g_Y [TOK*1536];
static __device__ float g_P [TOK*512];
static __device__ float g_x1[TOK*512];
static __device__ __nv_bfloat16 g_Ah[TOK*512];
static __device__ __nv_bfloat16 g_Al[TOK*512];
static __device__ __nv_bfloat16 g_Wh[1536*512];
static __device__ __nv_bfloat16 g_Wl[1536*512];
static __device__ float g_sts[32*32*2];
static __device__ float g_stt[1152*32*2];

static __device__ __forceinline__ uint32_t s2u(const void* p) {
    uint32_t a;
    asm("{ .reg .u64 t; cvta.to.shared.u64 t, %1; cvt.u32.u64 %0, t; }" : "=r"(a) : "l"(p));
    return a;
}
static __device__ __forceinline__ void ldm4(uint32_t* r, uint32_t addr) {
    asm volatile("ldmatrix.sync.aligned.m8n8.x4.shared.b16 {%0,%1,%2,%3}, [%4];"
        : "=r"(r[0]), "=r"(r[1]), "=r"(r[2]), "=r"(r[3]) : "r"(addr));
}
static __device__ __forceinline__ void mma16816(float* d, const uint32_t* a, uint32_t b0, uint32_t b1) {
    asm volatile("mma.sync.aligned.m16n8k16.row.col.f32.bf16.bf16.f32 "
        "{%0,%1,%2,%3}, {%4,%5,%6,%7}, {%8,%9}, {%0,%1,%2,%3};"
        : "+f"(d[0]), "+f"(d[1]), "+f"(d[2]), "+f"(d[3])
        : "r"(a[0]), "r"(a[1]), "r"(a[2]), "r"(a[3]), "r"(b0), "r"(b1));
}
static __device__ __forceinline__ void cpasync16(uint32_t saddr, const void* g) {
    asm volatile("cp.async.cg.shared.global [%0], [%1], 16;" :: "r"(saddr), "l"(g));
}
static __device__ __forceinline__ void split2(float v, __nv_bfloat16& h, __nv_bfloat16& l) {
    h = __float2bfloat16_rn(v);
    l = __float2bfloat16_rn(v - __bfloat162float(h));
}
static __device__ __forceinline__ uint32_t packbf(__nv_bfloat16 lo, __nv_bfloat16 hi) {
    __nv_bfloat162 t = __halves2bfloat162(lo, hi);
    return *reinterpret_cast<uint32_t*>(&t);
}

// ---------------- spatial GN stats ----------------
__global__ void gn_stats_s(const float* __restrict__ x) {
    int bt = blockIdx.x, g = blockIdx.y;
    int b = bt >> 4, t = bt & 15;
    const float* base = x + ((size_t)(b*512 + g*16))*9216 + (size_t)t*576;
    float s = 0.f, ss = 0.f;
    for (int e = threadIdx.x; e < 9216; e += 256) {
        int cc = e / 576, hw = e - cc*576;
        float v = base[(size_t)cc*9216 + hw];
        s += v; ss += v*v;
    }
    __shared__ float rs[8], rss[8];
    #pragma unroll
    for (int o = 16; o; o >>= 1) {
        s  += __shfl_xor_sync(0xffffffffu, s,  o);
        ss += __shfl_xor_sync(0xffffffffu, ss, o);
    }
    int w = threadIdx.x >> 5;
    if ((threadIdx.x & 31) == 0) { rs[w] = s; rss[w] = ss; }
    __syncthreads();
    if (threadIdx.x == 0) {
        s = 0.f; ss = 0.f;
        #pragma unroll
        for (int i = 0; i < 8; i++) { s += rs[i]; ss += rss[i]; }
        float mean = s * (1.f/9216.f);
        float var  = ss * (1.f/9216.f) - mean*mean;
        g_sts[(bt*32+g)*2+0] = mean;
        g_sts[(bt*32+g)*2+1] = rsqrtf(var + 1e-5f);
    }
}

// --------- normalize + transpose spatial -> hi/lo bf16 token-major ---------
__global__ void norm_tr_s(const float* __restrict__ x,
                          const float* __restrict__ gw, const float* __restrict__ gb) {
    __shared__ float tile[32][33];
    int bt = blockIdx.x, b = bt >> 4, t = bt & 15;
    int hw0 = blockIdx.y*32, c0 = blockIdx.z*32;
    int tx = threadIdx.x, ty = threadIdx.y;
    #pragma unroll
    for (int i = 0; i < 4; i++) {
        int cl = ty + i*8, c = c0 + cl;
        float mean = g_sts[(bt*32 + (c>>4))*2+0];
        float rstd = g_sts[(bt*32 + (c>>4))*2+1];
        float v = x[(((size_t)b*512 + c)*16 + t)*576 + hw0 + tx];
        tile[cl][tx] = (v - mean)*rstd*gw[c] + gb[c];
    }
    __syncthreads();
    #pragma unroll
    for (int i = 0; i < 4; i++) {
        int hwl = ty + i*8;
        size_t o = ((size_t)(bt*576 + hw0 + hwl))*512 + c0 + tx;
        __nv_bfloat16 h, l; split2(tile[tx][hwl], h, l);
        g_Ah[o] = h; g_Al[o] = l;
    }
}

// ---------------- weight split ----------------
__global__ void wsplit(const float* __restrict__ w, int n) {
    int i = blockIdx.x*256 + threadIdx.x;
    if (i < n) {
        __nv_bfloat16 h, l; split2(w[i], h, l);
        g_Wh[i] = h; g_Wl[i] = l;
    }
}

// ---------------- bf16x3 HMMA GEMM with cp.async 2-stage pipeline ----------------
#define SPAD 72
#define STAGE_B 73728   // 4 tiles * 128*72*2 bytes
__global__ __launch_bounds__(256) void gemm_mma(
    const __nv_bfloat16* __restrict__ Ah, const __nv_bfloat16* __restrict__ Al,
    const __nv_bfloat16* __restrict__ Bh, const __nv_bfloat16* __restrict__ Bl,
    const float* __restrict__ bias, float* __restrict__ C, int N) {
    extern __shared__ __nv_bfloat16 sm[];
    uint32_t smb = s2u(sm);
    int tid = threadIdx.x, wid = tid >> 5, lane = tid & 31;
    int wm = wid >> 2, wn = wid & 3;
    int m0 = blockIdx.y*128, n0 = blockIdx.x*128;
    const __nv_bfloat16* pAh = Ah + (size_t)m0*512;
    const __nv_bfloat16* pAl = Al + (size_t)m0*512;
    const __nv_bfloat16* pBh = Bh + (size_t)n0*512;
    const __nv_bfloat16* pBl = Bl + (size_t)n0*512;

    float acc[4][4][4];
    #pragma unroll
    for (int i = 0; i < 4; i++)
        #pragma unroll
        for (int j = 0; j < 4; j++)
            #pragma unroll
            for (int k = 0; k < 4; k++) acc[i][j][k] = 0.f;

    int lrow = lane & 15, lcol = (lane >> 4) << 3;
    uint32_t aoff = (uint32_t)(( (wm*64 + lrow) * SPAD + lcol ) * 2);
    uint32_t boff = (uint32_t)(( (wn*32 + lrow) * SPAD + lcol ) * 2);

    // prefetch chunk 0 into stage 0
    #pragma unroll
    for (int i = 0; i < 4; i++) {
        int idx = tid + i*256;
        int r = idx >> 3, c8 = (idx & 7) << 3;
        size_t go = (size_t)r*512 + c8;
        uint32_t so = smb + (uint32_t)((r*SPAD + c8)*2);
        cpasync16(so,             pAh + go);
        cpasync16(so + 18432,     pAl + go);
        cpasync16(so + 36864,     pBh + go);
        cpasync16(so + 55296,     pBl + go);
    }
    asm volatile("cp.async.commit_group;" ::: "memory");

    for (int chunk = 0; chunk < 8; chunk++) {
        if (chunk < 7) {
            int koff = (chunk+1)*64;
            uint32_t stb = smb + ((chunk+1)&1)*STAGE_B;
            #pragma unroll
            for (int i = 0; i < 4; i++) {
                int idx = tid + i*256;
                int r = idx >> 3, c8 = (idx & 7) << 3;
                size_t go = (size_t)r*512 + koff + c8;
                uint32_t so = stb + (uint32_t)((r*SPAD + c8)*2);
                cpasync16(so,             pAh + go);
                cpasync16(so + 18432,     pAl + go);
                cpasync16(so + 36864,     pBh + go);
                cpasync16(so + 55296,     pBl + go);
            }
            asm volatile("cp.async.commit_group;" ::: "memory");
            asm volatile("cp.async.wait_group 1;" ::: "memory");
        } else {
            asm volatile("cp.async.wait_group 0;" ::: "memory");
        }
        __syncthreads();
        uint32_t stb = smb + (chunk&1)*STAGE_B;
        uint32_t uAh = stb + aoff, uAl = stb + 18432 + aoff;
        uint32_t uBh = stb + 36864 + boff, uBl = stb + 55296 + boff;
        #pragma unroll
        for (int k16 = 0; k16 < 4; k16++) {
            uint32_t kb = k16*32;
            uint32_t ah[4][4], al[4][4], bh[2][4], bl[2][4];
            #pragma unroll
            for (int mi = 0; mi < 4; mi++) {
                ldm4(ah[mi], uAh + mi*16*SPAD*2 + kb);
                ldm4(al[mi], uAl + mi*16*SPAD*2 + kb);
            }
            #pragma unroll
            for (int nj = 0; nj < 2; nj++) {
                ldm4(bh[nj], uBh + nj*16*SPAD*2 + kb);
                ldm4(bl[nj], uBl + nj*16*SPAD*2 + kb);
            }
            #pragma unroll
            for (int mi = 0; mi < 4; mi++)
                #pragma unroll
                for (int ni = 0; ni < 4; ni++) {
                    int nj = ni >> 1, hf = ni & 1;
                    mma16816(acc[mi][ni], ah[mi], bh[nj][hf], bh[nj][hf+2]);
                    mma16816(acc[mi][ni], al[mi], bh[nj][hf], bh[nj][hf+2]);
                    mma16816(acc[mi][ni], ah[mi], bl[nj][hf], bl[nj][hf+2]);
                }
        }
        __syncthreads();
    }
    int rbase = m0 + wm*64 + (lane >> 2);
    int cbase = n0 + wn*32 + (lane & 3)*2;
    #pragma unroll
    for (int mi = 0; mi < 4; mi++)
        #pragma unroll
        for (int ni = 0; ni < 4; ni++) {
            int col = cbase + ni*8;
            float2 bv = *(const float2*)(bias + col);
            int r0 = rbase + mi*16;
            float2 o0 = { acc[mi][ni][0] + bv.x, acc[mi][ni][1] + bv.y };
            float2 o1 = { acc[mi][ni][2] + bv.x, acc[mi][ni][3] + bv.y };
            *(float2*)(C + (size_t)r0*N + col) = o0;
            *(float2*)(C + (size_t)(r0+8)*N + col) = o1;
        }
}

// ---------------- spatial flash attention (HMMA bf16x3) ----------------
// 128 threads, 4 warps; warp owns 16 q-rows x 64 cols. BQ=64, BKV=64, 9 chunks.
#define AT_SMEM (6*64*72*2)
__global__ __launch_bounds__(128) void attn_spatial_mma(const float* __restrict__ Y,
        __nv_bfloat16* __restrict__ Oh, __nv_bfloat16* __restrict__ Ol) {
    extern __shared__ __nv_bfloat16 sb[];
    __nv_bfloat16* Qh  = sb;
    __nv_bfloat16* Ql  = sb + 4608;
    __nv_bfloat16* Kh  = sb + 2*4608;
    __nv_bfloat16* Kl  = sb + 3*4608;
    __nv_bfloat16* Vth = sb + 4*4608;
    __nv_bfloat16* Vtl = sb + 5*4608;
    int q0 = blockIdx.x*64, h = blockIdx.y, ns = blockIdx.z;
    int tid = threadIdx.x, wid = tid >> 5, lane = tid & 31;

    {   // load Q once, fold s^2 = 0.125, split hi/lo
        int row = tid >> 1, dh = (tid & 1)*32;
        const float* src = Y + ((size_t)(ns*576 + q0 + row))*1536 + h*64 + dh;
        #pragma unroll
        for (int j = 0; j < 8; j++) {
            float4 v = *(const float4*)(src + j*4);
            float vv[4] = {v.x*0.125f, v.y*0.125f, v.z*0.125f, v.w*0.125f};
            #pragma unroll
            for (int e = 0; e < 4; e++) {
                __nv_bfloat16 hh, ll; split2(vv[e], hh, ll);
                Qh[row*72 + dh + j*4 + e] = hh;
                Ql[row*72 + dh + j*4 + e] = ll;
            }
        }
    }
    float oacc[8][4];
    float m[2] = {-1e30f, -1e30f}, l[2] = {0.f, 0.f};
    #pragma unroll
    for (int t = 0; t < 8; t++)
        #pragma unroll
        for (int e = 0; e < 4; e++) oacc[t][e] = 0.f;

    int lrow = lane & 15, lcol = (lane >> 4) << 3;
    uint32_t uQh = s2u(Qh) + ((wid*16 + lrow)*SPAD + lcol)*2;
    uint32_t uQl = s2u(Ql) + ((wid*16 + lrow)*SPAD + lcol)*2;
    uint32_t uKh = s2u(Kh) + (lrow*SPAD + lcol)*2;
    uint32_t uKl = s2u(Kl) + (lrow*SPAD + lcol)*2;
    uint32_t uVh = s2u(Vth) + (lrow*SPAD + lcol)*2;
    uint32_t uVl = s2u(Vtl) + (lrow*SPAD + lcol)*2;

    for (int ch = 0; ch < 9; ch++) {
        __syncthreads();
        {   // load K,V chunk; V stored transposed [d][kv]
            int row = tid >> 1, dh = (tid & 1)*32;
            const float* ksrc = Y + ((size_t)(ns*576 + ch*64 + row))*1536 + 512 + h*64 + dh;
            #pragma unroll
            for (int j = 0; j < 8; j++) {
                float4 kv = *(const float4*)(ksrc + j*4);
                float kk[4] = {kv.x, kv.y, kv.z, kv.w};
                float4 vv4 = *(const float4*)(ksrc + 512 + j*4);
                float vvv[4] = {vv4.x, vv4.y, vv4.z, vv4.w};
                #pragma unroll
                for (int e = 0; e < 4; e++) {
                    __nv_bfloat16 hh, ll;
                    split2(kk[e], hh, ll);
                    Kh[row*72 + dh + j*4 + e] = hh;
                    Kl[row*72 + dh + j*4 + e] = ll;
                    split2(vvv[e], hh, ll);
                    Vth[(dh + j*4 + e)*72 + row] = hh;
                    Vtl[(dh + j*4 + e)*72 + row] = ll;
                }
            }
        }
        __syncthreads();
        // S = Q*K^T (3-term compensation)
        float sacc[8][4];
        #pragma unroll
        for (int t = 0; t < 8; t++)
            #pragma unroll
            for (int e = 0; e < 4; e++) sacc[t][e] = 0.f;
        #pragma unroll
        for (int k16 = 0; k16 < 4; k16++) {
            uint32_t kb = k16*32;
            uint32_t ah[4], al[4];
            ldm4(ah, uQh + kb);
            ldm4(al, uQl + kb);
            #pragma unroll
            for (int g = 0; g < 4; g++) {
                uint32_t kh[4], kl[4];
                ldm4(kh, uKh + g*16*SPAD*2 + kb);
                ldm4(kl, uKl + g*16*SPAD*2 + kb);
                mma16816(sacc[2*g],   ah, kh[0], kh[2]);
                mma16816(sacc[2*g],   al, kh[0], kh[2]);
                mma16816(sacc[2*g],   ah, kl[0], kl[2]);
                mma16816(sacc[2*g+1], ah, kh[1], kh[3]);
                mma16816(sacc[2*g+1], al, kh[1], kh[3]);
                mma16816(sacc[2*g+1], ah, kl[1], kl[3]);
            }
        }
        // online softmax (rows warp-local; 4 lanes share a row)
        uint32_t phx[8][2], plx[8][2];
        #pragma unroll
        for (int hf = 0; hf < 2; hf++) {
            float mx = -1e30f;
            #pragma unroll
            for (int t = 0; t < 8; t++)
                mx = fmaxf(mx, fmaxf(sacc[t][2*hf], sacc[t][2*hf+1]));
            mx = fmaxf(mx, __shfl_xor_sync(0xffffffffu, mx, 1));
            mx = fmaxf(mx, __shfl_xor_sync(0xffffffffu, mx, 2));
            float nm = fmaxf(m[hf], mx);
            float alpha = __expf(m[hf] - nm);
            float rs = 0.f;
            #pragma unroll
            for (int t = 0; t < 8; t++) {
                float p0 = __expf(sacc[t][2*hf]   - nm);
                float p1 = __expf(sacc[t][2*hf+1] - nm);
                rs += p0 + p1;
                __nv_bfloat16 h0, l0, h1, l1;
                split2(p0, h0, l0); split2(p1, h1, l1);
                phx[t][hf] = packbf(h0, h1);
                plx[t][hf] = packbf(l0, l1);
            }
            rs += __shfl_xor_sync(0xffffffffu, rs, 1);
            rs += __shfl_xor_sync(0xffffffffu, rs, 2);
            l[hf] = l[hf]*alpha + rs;
            m[hf] = nm;
            #pragma unroll
            for (int t = 0; t < 8; t++) {
                oacc[t][2*hf]   *= alpha;
                oacc[t][2*hf+1] *= alpha;
            }
        }
        // O += P*V (3-term compensation)
        #pragma unroll
        for (int g = 0; g < 4; g++) {
            uint32_t pah[4] = {phx[2*g][0], phx[2*g][1], phx[2*g+1][0], phx[2*g+1][1]};
            uint32_t pal[4] = {plx[2*g][0], plx[2*g][1], plx[2*g+1][0], plx[2*g+1][1]};
            #pragma unroll
            for (int dt = 0; dt < 4; dt++) {
                uint32_t vh[4], vl[4];
                ldm4(vh, uVh + dt*16*SPAD*2 + g*32);
                ldm4(vl, uVl + dt*16*SPAD*2 + g*32);
                mma16816(oacc[2*dt],   pah, vh[0], vh[2]);
                mma16816(oacc[2*dt],   pal, vh[0], vh[2]);
                mma16816(oacc[2*dt],   pah, vl[0], vl[2]);
                mma16816(oacc[2*dt+1], pah, vh[1], vh[3]);
                mma16816(oacc[2*dt+1], pal, vh[1], vh[3]);
                mma16816(oacc[2*dt+1], pah, vl[1], vl[3]);
            }
        }
    }
    // normalize + write hi/lo bf16
    float inv0 = 1.f / l[0], inv1 = 1.f / l[1];
    int r0 = q0 + wid*16 + (lane >> 2);
    int col0 = h*64 + (lane & 3)*2;
    #pragma unroll
    for (int t = 0; t < 8; t++) {
        int col = col0 + t*8;
        __nv_bfloat16 h0, l0h, h1, l1h;
        split2(oacc[t][0]*inv0, h0, l0h);
        split2(oacc[t][1]*inv0, h1, l1h);
        size_t offA = ((size_t)(ns*576 + r0))*512 + col;
        *(__nv_bfloat162*)(Oh + offA) = __halves2bfloat162(h0, h1);
        *(__nv_bfloat162*)(Ol + offA) = __halves2bfloat162(l0h, l1h);
        split2(oacc[t][2]*inv1, h0, l0h);
        split2(oacc[t][3]*inv1, h1, l1h);
        size_t offB = ((size_t)(ns*576 + r0 + 8))*512 + col;
        *(__nv_bfloat162*)(Oh + offB) = __halves2bfloat162(h0, h1);
        *(__nv_bfloat162*)(Ol + offB) = __halves2bfloat162(l0h, l1h);
    }
}

// --------- spatial residual: x1 = x + transpose-back(g_P) ---------
__global__ void resid_s(const float* __restrict__ x) {
    __shared__ float tile[32][33];
    int bt = blockIdx.x, b = bt >> 4, t = bt & 15;
    int hw0 = blockIdx.y*32, c0 = blockIdx.z*32;
    int tx = threadIdx.x, ty = threadIdx.y;
    #pragma unroll
    for (int i = 0; i < 4; i++) {
        int hwl = ty + i*8;
        tile[tx][hwl] = g_P[((size_t)(bt*576 + hw0 + hwl))*512 + c0 + tx];
    }
    __syncthreads();
    #pragma unroll
    for (int i = 0; i < 4; i++) {
        int cl = ty + i*8;
        size_t idx = (((size_t)b*512 + c0 + cl)*16 + t)*576 + hw0 + tx;
        g_x1[idx] = x[idx] + tile[cl][tx];
    }
}

// ---------------- temporal GN stats ----------------
__global__ void gn_stats_t() {
    int b = blockIdx.x, g = blockIdx.y, hw = threadIdx.x;
    const float* base = g_x1 + ((size_t)b*512 + g*16)*9216 + hw;
    float s = 0.f, ss = 0.f;
    for (int cc = 0; cc < 16; cc++)
        #pragma unroll
        for (int t = 0; t < 16; t++) {
            float v = base[(size_t)cc*9216 + t*576];
            s += v; ss += v*v;
        }
    float mean = s*(1.f/256.f);
    float var  = ss*(1.f/256.f) - mean*mean;
    g_stt[((size_t)(b*576+hw)*32 + g)*2 + 0] = mean;
    g_stt[((size_t)(b*576+hw)*32 + g)*2 + 1] = rsqrtf(var + 1e-5f);
}

// --------- normalize + transpose temporal -> hi/lo bf16 token-major ---------
__global__ void norm_tr_t(const float* __restrict__ gw, const float* __restrict__ gb) {
    __shared__ float tile[32][33];
    int bt = blockIdx.x, b = bt >> 4, t = bt & 15;
    int hw0 = blockIdx.y*32, c0 = blockIdx.z*32;
    int tx = threadIdx.x, ty = threadIdx.y;
    #pragma unroll
    for (int i = 0; i < 4; i++) {
        int cl = ty + i*8, c = c0 + cl, hw = hw0 + tx;
        float mean = g_stt[((size_t)(b*576+hw)*32 + (c>>4))*2 + 0];
        float rstd = g_stt[((size_t)(b*576+hw)*32 + (c>>4))*2 + 1];
        float v = g_x1[(((size_t)b*512 + c)*16 + t)*576 + hw];
        tile[cl][tx] = (v - mean)*rstd*gw[c] + gb[c];
    }
    __syncthreads();
    #pragma unroll
    for (int i = 0; i < 4; i++) {
        int hwl = ty + i*8;
        size_t o = ((size_t)((b*576 + hw0 + hwl)*16 + t))*512 + c0 + tx;
        __nv_bfloat16 h, l; split2(tile[tx][hwl], h, l);
        g_Ah[o] = h; g_Al[o] = l;
    }
}

// ---------------- temporal attention ----------------
__global__ __launch_bounds__(256) void attn_temporal(const float* __restrict__ Y,
    const float* __restrict__ rpk, const float* __restrict__ rpv,
    __nv_bfloat16* __restrict__ Oh, __nv_bfloat16* __restrict__ Ol) {
    __shared__ float qs[16][68], ks[16][68], vs[16][68];
    __shared__ float pk[33][68], pvt[33][68], wsm[16][20];
    int h = blockIdx.x, samp = blockIdx.y, tid = threadIdx.x;
    for (int i = tid; i < 33*64; i += 256) {
        pk [i>>6][i&63] = rpk[i];
        pvt[i>>6][i&63] = rpv[i];
    }
    {
        int t = tid >> 4, d0 = (tid & 15)*4;
        const float* base = Y + ((size_t)(samp*16 + t))*1536 + h*64 + d0;
        float4 q4 = *(const float4*)(base);
        float4 k4 = *(const float4*)(base + 512);
        float4 v4 = *(const float4*)(base + 1024);
        qs[t][d0+0]=q4.x; qs[t][d0+1]=q4.y; qs[t][d0+2]=q4.z; qs[t][d0+3]=q4.w;
        ks[t][d0+0]=k4.x; ks[t][d0+1]=k4.y; ks[t][d0+2]=k4.z; ks[t][d0+3]=k4.w;
        vs[t][d0+0]=v4.x; vs[t][d0+1]=v4.y; vs[t][d0+2]=v4.z; vs[t][d0+3]=v4.w;
    }
    __syncthreads();
    {
        int t = tid >> 4, s = tid & 15;
        float wv = -1e30f;
        if (s <= t) {
            float a = 0.f, bb = 0.f;
            int ri = t - s + 16;
            for (int d = 0; d < 64; d++) {
                a  += qs[t][d]*ks[s][d];
                bb += qs[s][d]*pk[ri][d];
            }
            wv = 0.125f*a + SCALE*bb;
        }
        float mx = wv;
        #pragma unroll
        for (int o = 8; o; o >>= 1) mx = fmaxf(mx, __shfl_xor_sync(0xffffffffu, mx, o, 16));
        float e = (s <= t) ? __expf(wv - mx) : 0.f;
        float sum = e;
        #pragma unroll
        for (int o = 8; o; o >>= 1) sum += __shfl_xor_sync(0xffffffffu, sum, o, 16);
        wsm[t][s] = e / sum;
    }
    __syncthreads();
    {
        int t = tid >> 4, d0 = (tid & 15)*4;
        float o0 = 0.f, o1 = 0.f, o2 = 0.f, o3 = 0.f;
        #pragma unroll
        for (int s = 0; s < 16; s++) {
            float p = wsm[t][s];
            int ri = s - t + 16;
            o0 += p*(vs[s][d0+0] + pvt[ri][d0+0]);
            o1 += p*(vs[s][d0+1] + pvt[ri][d0+1]);
            o2 += p*(vs[s][d0+2] + pvt[ri][d0+2]);
            o3 += p*(vs[s][d0+3] + pvt[ri][d0+3]);
        }
        size_t off = ((size_t)(samp*16 + t))*512 + h*64 + d0;
        __nv_bfloat16 h0, l0, h1, l1, h2, l2, h3, l3;
        split2(o0, h0, l0); split2(o1, h1, l1);
        split2(o2, h2, l2); split2(o3, h3, l3);
        *(__nv_bfloat162*)(Oh + off)     = __halves2bfloat162(h0, h1);
        *(__nv_bfloat162*)(Oh + off + 2) = __halves2bfloat162(h2, h3);
        *(__nv_bfloat162*)(Ol + off)     = __halves2bfloat162(l0, l1);
        *(__nv_bfloat162*)(Ol + off + 2) = __halves2bfloat162(l2, l3);
    }
}

// --------- final add ---------
__global__ void final_add(float* __restrict__ out) {
    __shared__ float tile[32][33];
    int bt = blockIdx.x, b = bt >> 4, t = bt & 15;
    int hw0 = blockIdx.y*32, c0 = blockIdx.z*32;
    int tx = threadIdx.x, ty = threadIdx.y;
    #pragma unroll
    for (int i = 0; i < 4; i++) {
        int hwl = ty + i*8;
        tile[tx][hwl] = g_P[((size_t)((b*576 + hw0 + hwl)*16 + t))*512 + c0 + tx];
    }
    __syncthreads();
    #pragma unroll
    for (int i = 0; i < 4; i++) {
        int cl = ty + i*8;
        size_t idx = (((size_t)b*512 + c0 + cl)*16 + t)*576 + hw0 + tx;
        out[idx] = g_x1[idx] + tile[cl][tx];
    }
}

extern "C" void kernel_launch(void* const* d_in, const int* in_sizes, int n_in,
                              void* d_out, int out_size) {
    const float* x        = (const float*)d_in[0];
    const float* norm_s_w = (const float*)d_in[1];
    const float* norm_s_b = (const float*)d_in[2];
    const float* qkv_s_w  = (const float*)d_in[3];
    const float* qkv_s_b  = (const float*)d_in[4];
    const float* proj_s_w = (const float*)d_in[5];
    const float* proj_s_b = (const float*)d_in[6];
    const float* norm_t_w = (const float*)d_in[7];
    const float* norm_t_b = (const float*)d_in[8];
    const float* qkv_t_w  = (const float*)d_in[9];
    const float* qkv_t_b  = (const float*)d_in[10];
    const float* proj_t_w = (const float*)d_in[11];
    const float* proj_t_b = (const float*)d_in[12];
    const float* rpk      = (const float*)d_in[13];
    const float* rpv      = (const float*)d_in[14];
    float* out = (float*)d_out;

    float *gY, *gP;
    __nv_bfloat16 *gAh, *gAl, *gWh, *gWl;
    cudaGetSymbolAddress((void**)&gY,  g_Y);
    cudaGetSymbolAddress((void**)&gP,  g_P);
    cudaGetSymbolAddress((void**)&gAh, g_Ah);
    cudaGetSymbolAddress((void**)&gAl, g_Al);
    cudaGetSymbolAddress((void**)&gWh, g_Wh);
    cudaGetSymbolAddress((void**)&gWl, g_Wl);

    const int GEMM_SMEM = 2*STAGE_B;
    cudaFuncSetAttribute(gemm_mma, cudaFuncAttributeMaxDynamicSharedMemorySize, GEMM_SMEM);
    cudaFuncSetAttribute(attn_spatial_mma, cudaFuncAttributeMaxDynamicSharedMemorySize, AT_SMEM);

    dim3 tb(32, 8);
    dim3 tg(32, 18, 16);

    // spatial branch
    gn_stats_s<<<dim3(32,32), 256>>>(x);
    norm_tr_s<<<tg, tb>>>(x, norm_s_w, norm_s_b);
    wsplit<<<3072, 256>>>(qkv_s_w, 1536*512);
    gemm_mma<<<dim3(12,144), 256, GEMM_SMEM>>>(gAh, gAl, gWh, gWl, qkv_s_b, gY, 1536);
    attn_spatial_mma<<<dim3(9,8,32), 128, AT_SMEM>>>(gY, gAh, gAl);
    wsplit<<<1024, 256>>>(proj_s_w, 512*512);
    gemm_mma<<<dim3(4,144), 256, GEMM_SMEM>>>(gAh, gAl, gWh, gWl, proj_s_b, gP, 512);
    resid_s<<<tg, tb>>>(x);

    // temporal branch
    gn_stats_t<<<dim3(2,32), 576>>>();
    norm_tr_t<<<tg, tb>>>(norm_t_w, norm_t_b);
    wsplit<<<3072, 256>>>(qkv_t_w, 1536*512);
    gemm_mma<<<dim3(12,144), 256, GEMM_SMEM>>>(gAh, gAl, gWh, gWl, qkv_t_b, gY, 1536);
    attn_temporal<<<dim3(8,1152), 256>>>(gY, rpk, rpv, gAh, gAl);
    wsplit<<<1024, 256>>>(proj_t_w, 512*512);
    gemm_mma<<<dim3(4,144), 256, GEMM_SMEM>>>(gAh, gAl, gWh, gWl, proj_t_b, gP, 512);
    final_add<<<tg, tb>>>(out);
}

// round 6
// speedup vs baseline: 1.7189x; 1.0053x over previous
#include <cuda_runtime.h>
#include <cuda_bf16.h>
#include <stdint.h>
#include <math.h>

#define TOK 18432
#define SCALE 0.35355339059327373f

static __device__ float g_Y [TOK*1536];
static __device__ float g_P [TOK*512];
static __device__ float g_x1[TOK*512];
static __device__ __nv_bfloat16 g_Ah[TOK*512];
static __device__ __nv_bfloat16 g_Al[TOK*512];
static __device__ __nv_bfloat16 g_Wh[1536*512];
static __device__ __nv_bfloat16 g_Wl[1536*512];
static __device__ float g_sts[32*32*2];
static __device__ float g_stt[1152*32*2];

static __device__ __forceinline__ uint32_t s2u(const void* p) {
    uint32_t a;
    asm("{ .reg .u64 t; cvta.to.shared.u64 t, %1; cvt.u32.u64 %0, t; }" : "=r"(a) : "l"(p));
    return a;
}
static __device__ __forceinline__ void ldm4(uint32_t* r, uint32_t addr) {
    asm volatile("ldmatrix.sync.aligned.m8n8.x4.shared.b16 {%0,%1,%2,%3}, [%4];"
        : "=r"(r[0]), "=r"(r[1]), "=r"(r[2]), "=r"(r[3]) : "r"(addr));
}
static __device__ __forceinline__ void mma16816(float* d, const uint32_t* a, uint32_t b0, uint32_t b1) {
    asm volatile("mma.sync.aligned.m16n8k16.row.col.f32.bf16.bf16.f32 "
        "{%0,%1,%2,%3}, {%4,%5,%6,%7}, {%8,%9}, {%0,%1,%2,%3};"
        : "+f"(d[0]), "+f"(d[1]), "+f"(d[2]), "+f"(d[3])
        : "r"(a[0]), "r"(a[1]), "r"(a[2]), "r"(a[3]), "r"(b0), "r"(b1));
}
static __device__ __forceinline__ void cpasync16(uint32_t saddr, const void* g) {
    asm volatile("cp.async.cg.shared.global [%0], [%1], 16;" :: "r"(saddr), "l"(g));
}
static __device__ __forceinline__ void split2(float v, __nv_bfloat16& h, __nv_bfloat16& l) {
    h = __float2bfloat16_rn(v);
    l = __float2bfloat16_rn(v - __bfloat162float(h));
}
static __device__ __forceinline__ uint32_t packbf(__nv_bfloat16 lo, __nv_bfloat16 hi) {
    __nv_bfloat162 t = __halves2bfloat162(lo, hi);
    return *reinterpret_cast<uint32_t*>(&t);
}

// ---------------- spatial GN stats ----------------
__global__ void gn_stats_s(const float* __restrict__ x) {
    int bt = blockIdx.x, g = blockIdx.y;
    int b = bt >> 4, t = bt & 15;
    const float* base = x + ((size_t)(b*512 + g*16))*9216 + (size_t)t*576;
    float s = 0.f, ss = 0.f;
    for (int e = threadIdx.x; e < 9216; e += 256) {
        int cc = e / 576, hw = e - cc*576;
        float v = base[(size_t)cc*9216 + hw];
        s += v; ss += v*v;
    }
    __shared__ float rs[8], rss[8];
    #pragma unroll
    for (int o = 16; o; o >>= 1) {
        s  += __shfl_xor_sync(0xffffffffu, s,  o);
        ss += __shfl_xor_sync(0xffffffffu, ss, o);
    }
    int w = threadIdx.x >> 5;
    if ((threadIdx.x & 31) == 0) { rs[w] = s; rss[w] = ss; }
    __syncthreads();
    if (threadIdx.x == 0) {
        s = 0.f; ss = 0.f;
        #pragma unroll
        for (int i = 0; i < 8; i++) { s += rs[i]; ss += rss[i]; }
        float mean = s * (1.f/9216.f);
        float var  = ss * (1.f/9216.f) - mean*mean;
        g_sts[(bt*32+g)*2+0] = mean;
        g_sts[(bt*32+g)*2+1] = rsqrtf(var + 1e-5f);
    }
}

// --------- normalize + transpose spatial -> hi/lo bf16 token-major ---------
__global__ void norm_tr_s(const float* __restrict__ x,
                          const float* __restrict__ gw, const float* __restrict__ gb) {
    __shared__ float tile[32][33];
    int bt = blockIdx.x, b = bt >> 4, t = bt & 15;
    int hw0 = blockIdx.y*32, c0 = blockIdx.z*32;
    int tx = threadIdx.x, ty = threadIdx.y;
    #pragma unroll
    for (int i = 0; i < 4; i++) {
        int cl = ty + i*8, c = c0 + cl;
        float mean = g_sts[(bt*32 + (c>>4))*2+0];
        float rstd = g_sts[(bt*32 + (c>>4))*2+1];
        float v = x[(((size_t)b*512 + c)*16 + t)*576 + hw0 + tx];
        tile[cl][tx] = (v - mean)*rstd*gw[c] + gb[c];
    }
    __syncthreads();
    #pragma unroll
    for (int i = 0; i < 4; i++) {
        int hwl = ty + i*8;
        size_t o = ((size_t)(bt*576 + hw0 + hwl))*512 + c0 + tx;
        __nv_bfloat16 h, l; split2(tile[tx][hwl], h, l);
        g_Ah[o] = h; g_Al[o] = l;
    }
}

// ---------------- weight split ----------------
__global__ void wsplit(const float* __restrict__ w, int n) {
    int i = blockIdx.x*256 + threadIdx.x;
    if (i < n) {
        __nv_bfloat16 h, l; split2(w[i], h, l);
        g_Wh[i] = h; g_Wl[i] = l;
    }
}

// ---------------- bf16x3 HMMA GEMM, K-chunk 32, 2-stage cp.async, 2 CTAs/SM ----------------
#define GPAD 40
#define TILE_B 10240          // 128*40*2
#define STAGE_B 40960         // 4 tiles
__global__ __launch_bounds__(256) void gemm_mma(
    const __nv_bfloat16* __restrict__ Ah, const __nv_bfloat16* __restrict__ Al,
    const __nv_bfloat16* __restrict__ Bh, const __nv_bfloat16* __restrict__ Bl,
    const float* __restrict__ bias, float* __restrict__ C, int N) {
    extern __shared__ __nv_bfloat16 sm[];
    uint32_t smb = s2u(sm);
    int tid = threadIdx.x, wid = tid >> 5, lane = tid & 31;
    int wm = wid >> 2, wn = wid & 3;
    int m0 = blockIdx.y*128, n0 = blockIdx.x*128;
    const __nv_bfloat16* pAh = Ah + (size_t)m0*512;
    const __nv_bfloat16* pAl = Al + (size_t)m0*512;
    const __nv_bfloat16* pBh = Bh + (size_t)n0*512;
    const __nv_bfloat16* pBl = Bl + (size_t)n0*512;

    float acc[4][4][4];
    #pragma unroll
    for (int i = 0; i < 4; i++)
        #pragma unroll
        for (int j = 0; j < 4; j++)
            #pragma unroll
            for (int k = 0; k < 4; k++) acc[i][j][k] = 0.f;

    int lrow = lane & 15, lcol = (lane >> 4) << 3;
    uint32_t aoff = (uint32_t)(( (wm*64 + lrow) * GPAD + lcol ) * 2);
    uint32_t boff = (uint32_t)(( (wn*32 + lrow) * GPAD + lcol ) * 2);

    // prefetch chunk 0
    #pragma unroll
    for (int i = 0; i < 2; i++) {
        int idx = tid + i*256;
        int r = idx >> 2, c = idx & 3;
        size_t go = (size_t)r*512 + c*8;
        uint32_t so = smb + (uint32_t)(r*80 + c*16);
        cpasync16(so,            pAh + go);
        cpasync16(so + TILE_B,   pAl + go);
        cpasync16(so + 2*TILE_B, pBh + go);
        cpasync16(so + 3*TILE_B, pBl + go);
    }
    asm volatile("cp.async.commit_group;" ::: "memory");

    for (int chunk = 0; chunk < 16; chunk++) {
        if (chunk < 15) {
            int koff = (chunk+1)*32;
            uint32_t stb = smb + ((chunk+1)&1)*STAGE_B;
            #pragma unroll
            for (int i = 0; i < 2; i++) {
                int idx = tid + i*256;
                int r = idx >> 2, c = idx & 3;
                size_t go = (size_t)r*512 + koff + c*8;
                uint32_t so = stb + (uint32_t)(r*80 + c*16);
                cpasync16(so,            pAh + go);
                cpasync16(so + TILE_B,   pAl + go);
                cpasync16(so + 2*TILE_B, pBh + go);
                cpasync16(so + 3*TILE_B, pBl + go);
            }
            asm volatile("cp.async.commit_group;" ::: "memory");
            asm volatile("cp.async.wait_group 1;" ::: "memory");
        } else {
            asm volatile("cp.async.wait_group 0;" ::: "memory");
        }
        __syncthreads();
        uint32_t stb = smb + (chunk&1)*STAGE_B;
        uint32_t uAh = stb + aoff, uAl = stb + TILE_B + aoff;
        uint32_t uBh = stb + 2*TILE_B + boff, uBl = stb + 3*TILE_B + boff;
        #pragma unroll
        for (int k16 = 0; k16 < 2; k16++) {
            uint32_t kb = k16*32;
            uint32_t ah[4][4], al[4][4], bh[2][4], bl[2][4];
            #pragma unroll
            for (int mi = 0; mi < 4; mi++) {
                ldm4(ah[mi], uAh + mi*16*GPAD*2 + kb);
                ldm4(al[mi], uAl + mi*16*GPAD*2 + kb);
            }
            #pragma unroll
            for (int nj = 0; nj < 2; nj++) {
                ldm4(bh[nj], uBh + nj*16*GPAD*2 + kb);
                ldm4(bl[nj], uBl + nj*16*GPAD*2 + kb);
            }
            #pragma unroll
            for (int mi = 0; mi < 4; mi++)
                #pragma unroll
                for (int ni = 0; ni < 4; ni++) {
                    int nj = ni >> 1, hf = ni & 1;
                    mma16816(acc[mi][ni], ah[mi], bh[nj][hf], bh[nj][hf+2]);
                    mma16816(acc[mi][ni], al[mi], bh[nj][hf], bh[nj][hf+2]);
                    mma16816(acc[mi][ni], ah[mi], bl[nj][hf], bl[nj][hf+2]);
                }
        }
        __syncthreads();
    }
    int rbase = m0 + wm*64 + (lane >> 2);
    int cbase = n0 + wn*32 + (lane & 3)*2;
    #pragma unroll
    for (int mi = 0; mi < 4; mi++)
        #pragma unroll
        for (int ni = 0; ni < 4; ni++) {
            int col = cbase + ni*8;
            float2 bv = *(const float2*)(bias + col);
            int r0 = rbase + mi*16;
            float2 o0 = { acc[mi][ni][0] + bv.x, acc[mi][ni][1] + bv.y };
            float2 o1 = { acc[mi][ni][2] + bv.x, acc[mi][ni][3] + bv.y };
            *(float2*)(C + (size_t)r0*N + col) = o0;
            *(float2*)(C + (size_t)(r0+8)*N + col) = o1;
        }
}

// ---------------- spatial flash attention (HMMA bf16x3) ----------------
#define SPAD 72
#define AT_SMEM (6*64*72*2)
__global__ __launch_bounds__(128) void attn_spatial_mma(const float* __restrict__ Y,
        __nv_bfloat16* __restrict__ Oh, __nv_bfloat16* __restrict__ Ol) {
    extern __shared__ __nv_bfloat16 sb[];
    __nv_bfloat16* Qh  = sb;
    __nv_bfloat16* Ql  = sb + 4608;
    __nv_bfloat16* Kh  = sb + 2*4608;
    __nv_bfloat16* Kl  = sb + 3*4608;
    __nv_bfloat16* Vth = sb + 4*4608;
    __nv_bfloat16* Vtl = sb + 5*4608;
    int q0 = blockIdx.x*64, h = blockIdx.y, ns = blockIdx.z;
    int tid = threadIdx.x, wid = tid >> 5, lane = tid & 31;

    {
        int row = tid >> 1, dh = (tid & 1)*32;
        const float* src = Y + ((size_t)(ns*576 + q0 + row))*1536 + h*64 + dh;
        #pragma unroll
        for (int j = 0; j < 8; j++) {
            float4 v = *(const float4*)(src + j*4);
            float vv[4] = {v.x*0.125f, v.y*0.125f, v.z*0.125f, v.w*0.125f};
            #pragma unroll
            for (int e = 0; e < 4; e++) {
                __nv_bfloat16 hh, ll; split2(vv[e], hh, ll);
                Qh[row*72 + dh + j*4 + e] = hh;
                Ql[row*72 + dh + j*4 + e] = ll;
            }
        }
    }
    float oacc[8][4];
    float m[2] = {-1e30f, -1e30f}, l[2] = {0.f, 0.f};
    #pragma unroll
    for (int t = 0; t < 8; t++)
        #pragma unroll
        for (int e = 0; e < 4; e++) oacc[t][e] = 0.f;

    int lrow = lane & 15, lcol = (lane >> 4) << 3;
    uint32_t uQh = s2u(Qh) + ((wid*16 + lrow)*SPAD + lcol)*2;
    uint32_t uQl = s2u(Ql) + ((wid*16 + lrow)*SPAD + lcol)*2;
    uint32_t uKh = s2u(Kh) + (lrow*SPAD + lcol)*2;
    uint32_t uKl = s2u(Kl) + (lrow*SPAD + lcol)*2;
    uint32_t uVh = s2u(Vth) + (lrow*SPAD + lcol)*2;
    uint32_t uVl = s2u(Vtl) + (lrow*SPAD + lcol)*2;

    for (int ch = 0; ch < 9; ch++) {
        __syncthreads();
        {
            int row = tid >> 1, dh = (tid & 1)*32;
            const float* ksrc = Y + ((size_t)(ns*576 + ch*64 + row))*1536 + 512 + h*64 + dh;
            #pragma unroll
            for (int j = 0; j < 8; j++) {
                float4 kv = *(const float4*)(ksrc + j*4);
                float kk[4] = {kv.x, kv.y, kv.z, kv.w};
                float4 vv4 = *(const float4*)(ksrc + 512 + j*4);
                float vvv[4] = {vv4.x, vv4.y, vv4.z, vv4.w};
                #pragma unroll
                for (int e = 0; e < 4; e++) {
                    __nv_bfloat16 hh, ll;
                    split2(kk[e], hh, ll);
                    Kh[row*72 + dh + j*4 + e] = hh;
                    Kl[row*72 + dh + j*4 + e] = ll;
                    split2(vvv[e], hh, ll);
                    Vth[(dh + j*4 + e)*72 + row] = hh;
                    Vtl[(dh + j*4 + e)*72 + row] = ll;
                }
            }
        }
        __syncthreads();
        float sacc[8][4];
        #pragma unroll
        for (int t = 0; t < 8; t++)
            #pragma unroll
            for (int e = 0; e < 4; e++) sacc[t][e] = 0.f;
        #pragma unroll
        for (int k16 = 0; k16 < 4; k16++) {
            uint32_t kb = k16*32;
            uint32_t ah[4], al[4];
            ldm4(ah, uQh + kb);
            ldm4(al, uQl + kb);
            #pragma unroll
            for (int g = 0; g < 4; g++) {
                uint32_t kh[4], kl[4];
                ldm4(kh, uKh + g*16*SPAD*2 + kb);
                ldm4(kl, uKl + g*16*SPAD*2 + kb);
                mma16816(sacc[2*g],   ah, kh[0], kh[2]);
                mma16816(sacc[2*g],   al, kh[0], kh[2]);
                mma16816(sacc[2*g],   ah, kl[0], kl[2]);
                mma16816(sacc[2*g+1], ah, kh[1], kh[3]);
                mma16816(sacc[2*g+1], al, kh[1], kh[3]);
                mma16816(sacc[2*g+1], ah, kl[1], kl[3]);
            }
        }
        uint32_t phx[8][2], plx[8][2];
        #pragma unroll
        for (int hf = 0; hf < 2; hf++) {
            float mx = -1e30f;
            #pragma unroll
            for (int t = 0; t < 8; t++)
                mx = fmaxf(mx, fmaxf(sacc[t][2*hf], sacc[t][2*hf+1]));
            mx = fmaxf(mx, __shfl_xor_sync(0xffffffffu, mx, 1));
            mx = fmaxf(mx, __shfl_xor_sync(0xffffffffu, mx, 2));
            float nm = fmaxf(m[hf], mx);
            float alpha = __expf(m[hf] - nm);
            float rs = 0.f;
            #pragma unroll
            for (int t = 0; t < 8; t++) {
                float p0 = __expf(sacc[t][2*hf]   - nm);
                float p1 = __expf(sacc[t][2*hf+1] - nm);
                rs += p0 + p1;
                __nv_bfloat16 h0, l0, h1, l1;
                split2(p0, h0, l0); split2(p1, h1, l1);
                phx[t][hf] = packbf(h0, h1);
                plx[t][hf] = packbf(l0, l1);
            }
            rs += __shfl_xor_sync(0xffffffffu, rs, 1);
            rs += __shfl_xor_sync(0xffffffffu, rs, 2);
            l[hf] = l[hf]*alpha + rs;
            m[hf] = nm;
            #pragma unroll
            for (int t = 0; t < 8; t++) {
                oacc[t][2*hf]   *= alpha;
                oacc[t][2*hf+1] *= alpha;
            }
        }
        #pragma unroll
        for (int g = 0; g < 4; g++) {
            uint32_t pah[4] = {phx[2*g][0], phx[2*g][1], phx[2*g+1][0], phx[2*g+1][1]};
            uint32_t pal[4] = {plx[2*g][0], plx[2*g][1], plx[2*g+1][0], plx[2*g+1][1]};
            #pragma unroll
            for (int dt = 0; dt < 4; dt++) {
                uint32_t vh[4], vl[4];
                ldm4(vh, uVh + dt*16*SPAD*2 + g*32);
                ldm4(vl, uVl + dt*16*SPAD*2 + g*32);
                mma16816(oacc[2*dt],   pah, vh[0], vh[2]);
                mma16816(oacc[2*dt],   pal, vh[0], vh[2]);
                mma16816(oacc[2*dt],   pah, vl[0], vl[2]);
                mma16816(oacc[2*dt+1], pah, vh[1], vh[3]);
                mma16816(oacc[2*dt+1], pal, vh[1], vh[3]);
                mma16816(oacc[2*dt+1], pah, vl[1], vl[3]);
            }
        }
    }
    float inv0 = 1.f / l[0], inv1 = 1.f / l[1];
    int r0 = q0 + wid*16 + (lane >> 2);
    int col0 = h*64 + (lane & 3)*2;
    #pragma unroll
    for (int t = 0; t < 8; t++) {
        int col = col0 + t*8;
        __nv_bfloat16 h0, l0h, h1, l1h;
        split2(oacc[t][0]*inv0, h0, l0h);
        split2(oacc[t][1]*inv0, h1, l1h);
        size_t offA = ((size_t)(ns*576 + r0))*512 + col;
        *(__nv_bfloat162*)(Oh + offA) = __halves2bfloat162(h0, h1);
        *(__nv_bfloat162*)(Ol + offA) = __halves2bfloat162(l0h, l1h);
        split2(oacc[t][2]*inv1, h0, l0h);
        split2(oacc[t][3]*inv1, h1, l1h);
        size_t offB = ((size_t)(ns*576 + r0 + 8))*512 + col;
        *(__nv_bfloat162*)(Oh + offB) = __halves2bfloat162(h0, h1);
        *(__nv_bfloat162*)(Ol + offB) = __halves2bfloat162(l0h, l1h);
    }
}

// --------- spatial residual: x1 = x + transpose-back(g_P) ---------
__global__ void resid_s(const float* __restrict__ x) {
    __shared__ float tile[32][33];
    int bt = blockIdx.x, b = bt >> 4, t = bt & 15;
    int hw0 = blockIdx.y*32, c0 = blockIdx.z*32;
    int tx = threadIdx.x, ty = threadIdx.y;
    #pragma unroll
    for (int i = 0; i < 4; i++) {
        int hwl = ty + i*8;
        tile[tx][hwl] = g_P[((size_t)(bt*576 + hw0 + hwl))*512 + c0 + tx];
    }
    __syncthreads();
    #pragma unroll
    for (int i = 0; i < 4; i++) {
        int cl = ty + i*8;
        size_t idx = (((size_t)b*512 + c0 + cl)*16 + t)*576 + hw0 + tx;
        g_x1[idx] = x[idx] + tile[cl][tx];
    }
}

// ---------------- temporal GN stats ----------------
__global__ void gn_stats_t() {
    int b = blockIdx.x, g = blockIdx.y, hw = threadIdx.x;
    const float* base = g_x1 + ((size_t)b*512 + g*16)*9216 + hw;
    float s = 0.f, ss = 0.f;
    for (int cc = 0; cc < 16; cc++)
        #pragma unroll
        for (int t = 0; t < 16; t++) {
            float v = base[(size_t)cc*9216 + t*576];
            s += v; ss += v*v;
        }
    float mean = s*(1.f/256.f);
    float var  = ss*(1.f/256.f) - mean*mean;
    g_stt[((size_t)(b*576+hw)*32 + g)*2 + 0] = mean;
    g_stt[((size_t)(b*576+hw)*32 + g)*2 + 1] = rsqrtf(var + 1e-5f);
}

// --------- normalize + transpose temporal -> hi/lo bf16 token-major ---------
__global__ void norm_tr_t(const float* __restrict__ gw, const float* __restrict__ gb) {
    __shared__ float tile[32][33];
    int bt = blockIdx.x, b = bt >> 4, t = bt & 15;
    int hw0 = blockIdx.y*32, c0 = blockIdx.z*32;
    int tx = threadIdx.x, ty = threadIdx.y;
    #pragma unroll
    for (int i = 0; i < 4; i++) {
        int cl = ty + i*8, c = c0 + cl, hw = hw0 + tx;
        float mean = g_stt[((size_t)(b*576+hw)*32 + (c>>4))*2 + 0];
        float rstd = g_stt[((size_t)(b*576+hw)*32 + (c>>4))*2 + 1];
        float v = g_x1[(((size_t)b*512 + c)*16 + t)*576 + hw];
        tile[cl][tx] = (v - mean)*rstd*gw[c] + gb[c];
    }
    __syncthreads();
    #pragma unroll
    for (int i = 0; i < 4; i++) {
        int hwl = ty + i*8;
        size_t o = ((size_t)((b*576 + hw0 + hwl)*16 + t))*512 + c0 + tx;
        __nv_bfloat16 h, l; split2(tile[tx][hwl], h, l);
        g_Ah[o] = h; g_Al[o] = l;
    }
}

// ---------------- temporal attention ----------------
__global__ __launch_bounds__(256) void attn_temporal(const float* __restrict__ Y,
    const float* __restrict__ rpk, const float* __restrict__ rpv,
    __nv_bfloat16* __restrict__ Oh, __nv_bfloat16* __restrict__ Ol) {
    __shared__ float qs[16][68], ks[16][68], vs[16][68];
    __shared__ float pk[33][68], pvt[33][68], wsm[16][20];
    int h = blockIdx.x, samp = blockIdx.y, tid = threadIdx.x;
    for (int i = tid; i < 33*64; i += 256) {
        pk [i>>6][i&63] = rpk[i];
        pvt[i>>6][i&63] = rpv[i];
    }
    {
        int t = tid >> 4, d0 = (tid & 15)*4;
        const float* base = Y + ((size_t)(samp*16 + t))*1536 + h*64 + d0;
        float4 q4 = *(const float4*)(base);
        float4 k4 = *(const float4*)(base + 512);
        float4 v4 = *(const float4*)(base + 1024);
        qs[t][d0+0]=q4.x; qs[t][d0+1]=q4.y; qs[t][d0+2]=q4.z; qs[t][d0+3]=q4.w;
        ks[t][d0+0]=k4.x; ks[t][d0+1]=k4.y; ks[t][d0+2]=k4.z; ks[t][d0+3]=k4.w;
        vs[t][d0+0]=v4.x; vs[t][d0+1]=v4.y; vs[t][d0+2]=v4.z; vs[t][d0+3]=v4.w;
    }
    __syncthreads();
    {
        int t = tid >> 4, s = tid & 15;
        float wv = -1e30f;
        if (s <= t) {
            float a = 0.f, bb = 0.f;
            int ri = t - s + 16;
            for (int d = 0; d < 64; d++) {
                a  += qs[t][d]*ks[s][d];
                bb += qs[s][d]*pk[ri][d];
            }
            wv = 0.125f*a + SCALE*bb;
        }
        float mx = wv;
        #pragma unroll
        for (int o = 8; o; o >>= 1) mx = fmaxf(mx, __shfl_xor_sync(0xffffffffu, mx, o, 16));
        float e = (s <= t) ? __expf(wv - mx) : 0.f;
        float sum = e;
        #pragma unroll
        for (int o = 8; o; o >>= 1) sum += __shfl_xor_sync(0xffffffffu, sum, o, 16);
        wsm[t][s] = e / sum;
    }
    __syncthreads();
    {
        int t = tid >> 4, d0 = (tid & 15)*4;
        float o0 = 0.f, o1 = 0.f, o2 = 0.f, o3 = 0.f;
        #pragma unroll
        for (int s = 0; s < 16; s++) {
            float p = wsm[t][s];
            int ri = s - t + 16;
            o0 += p*(vs[s][d0+0] + pvt[ri][d0+0]);
            o1 += p*(vs[s][d0+1] + pvt[ri][d0+1]);
            o2 += p*(vs[s][d0+2] + pvt[ri][d0+2]);
            o3 += p*(vs[s][d0+3] + pvt[ri][d0+3]);
        }
        size_t off = ((size_t)(samp*16 + t))*512 + h*64 + d0;
        __nv_bfloat16 h0, l0, h1, l1, h2, l2, h3, l3;
        split2(o0, h0, l0); split2(o1, h1, l1);
        split2(o2, h2, l2); split2(o3, h3, l3);
        *(__nv_bfloat162*)(Oh + off)     = __halves2bfloat162(h0, h1);
        *(__nv_bfloat162*)(Oh + off + 2) = __halves2bfloat162(h2, h3);
        *(__nv_bfloat162*)(Ol + off)     = __halves2bfloat162(l0, l1);
        *(__nv_bfloat162*)(Ol + off + 2) = __halves2bfloat162(l2, l3);
    }
}

// --------- final add ---------
__global__ void final_add(float* __restrict__ out) {
    __shared__ float tile[32][33];
    int bt = blockIdx.x, b = bt >> 4, t = bt & 15;
    int hw0 = blockIdx.y*32, c0 = blockIdx.z*32;
    int tx = threadIdx.x, ty = threadIdx.y;
    #pragma unroll
    for (int i = 0; i < 4; i++) {
        int hwl = ty + i*8;
        tile[tx][hwl] = g_P[((size_t)((b*576 + hw0 + hwl)*16 + t))*512 + c0 + tx];
    }
    __syncthreads();
    #pragma unroll
    for (int i = 0; i < 4; i++) {
        int cl = ty + i*8;
        size_t idx = (((size_t)b*512 + c0 + cl)*16 + t)*576 + hw0 + tx;
        out[idx] = g_x1[idx] + tile[cl][tx];
    }
}

extern "C" void kernel_launch(void* const* d_in, const int* in_sizes, int n_in,
                              void* d_out, int out_size) {
    const float* x        = (const float*)d_in[0];
    const float* norm_s_w = (const float*)d_in[1];
    const float* norm_s_b = (const float*)d_in[2];
    const float* qkv_s_w  = (const float*)d_in[3];
    const float* qkv_s_b  = (const float*)d_in[4];
    const float* proj_s_w = (const float*)d_in[5];
    const float* proj_s_b = (const float*)d_in[6];
    const float* norm_t_w = (const float*)d_in[7];
    const float* norm_t_b = (const float*)d_in[8];
    const float* qkv_t_w  = (const float*)d_in[9];
    const float* qkv_t_b  = (const float*)d_in[10];
    const float* proj_t_w = (const float*)d_in[11];
    const float* proj_t_b = (const float*)d_in[12];
    const float* rpk      = (const float*)d_in[13];
    const float* rpv      = (const float*)d_in[14];
    float* out = (float*)d_out;

    float *gY, *gP;
    __nv_bfloat16 *gAh, *gAl, *gWh, *gWl;
    cudaGetSymbolAddress((void**)&gY,  g_Y);
    cudaGetSymbolAddress((void**)&gP,  g_P);
    cudaGetSymbolAddress((void**)&gAh, g_Ah);
    cudaGetSymbolAddress((void**)&gAl, g_Al);
    cudaGetSymbolAddress((void**)&gWh, g_Wh);
    cudaGetSymbolAddress((void**)&gWl, g_Wl);

    const int GEMM_SMEM = 2*STAGE_B;
    cudaFuncSetAttribute(gemm_mma, cudaFuncAttributeMaxDynamicSharedMemorySize, GEMM_SMEM);
    cudaFuncSetAttribute(attn_spatial_mma, cudaFuncAttributeMaxDynamicSharedMemorySize, AT_SMEM);

    dim3 tb(32, 8);
    dim3 tg(32, 18, 16);

    // spatial branch
    gn_stats_s<<<dim3(32,32), 256>>>(x);
    norm_tr_s<<<tg, tb>>>(x, norm_s_w, norm_s_b);
    wsplit<<<3072, 256>>>(qkv_s_w, 1536*512);
    gemm_mma<<<dim3(12,144), 256, GEMM_SMEM>>>(gAh, gAl, gWh, gWl, qkv_s_b, gY, 1536);
    attn_spatial_mma<<<dim3(9,8,32), 128, AT_SMEM>>>(gY, gAh, gAl);
    wsplit<<<1024, 256>>>(proj_s_w, 512*512);
    gemm_mma<<<dim3(4,144), 256, GEMM_SMEM>>>(gAh, gAl, gWh, gWl, proj_s_b, gP, 512);
    resid_s<<<tg, tb>>>(x);

    // temporal branch
    gn_stats_t<<<dim3(2,32), 576>>>();
    norm_tr_t<<<tg, tb>>>(norm_t_w, norm_t_b);
    wsplit<<<3072, 256>>>(qkv_t_w, 1536*512);
    gemm_mma<<<dim3(12,144), 256, GEMM_SMEM>>>(gAh, gAl, gWh, gWl, qkv_t_b, gY, 1536);
    attn_temporal<<<dim3(8,1152), 256>>>(gY, rpk, rpv, gAh, gAl);
    wsplit<<<1024, 256>>>(proj_t_w, 512*512);
    gemm_mma<<<dim3(4,144), 256, GEMM_SMEM>>>(gAh, gAl, gWh, gWl, proj_t_b, gP, 512);
    final_add<<<tg, tb>>>(out);
}

// round 7
// speedup vs baseline: 1.8280x; 1.0635x over previous
#include <cuda_runtime.h>
#include <cuda_bf16.h>
#include <stdint.h>
#include <math.h>

#define TOK 18432
#define SCALE 0.35355339059327373f
#define WOFF (1536*512)

static __device__ float g_Y [TOK*1536];
static __device__ float g_P [TOK*512];
static __device__ float g_x1[TOK*512];
static __device__ __nv_bfloat16 g_Ah[TOK*512];
static __device__ __nv_bfloat16 g_Al[TOK*512];
static __device__ __nv_bfloat16 g_Wh[2048*512];
static __device__ __nv_bfloat16 g_Wl[2048*512];
static __device__ float g_sts[32*32*2];
static __device__ float g_stt[1152*32*2];

static __device__ __forceinline__ uint32_t s2u(const void* p) {
    uint32_t a;
    asm("{ .reg .u64 t; cvta.to.shared.u64 t, %1; cvt.u32.u64 %0, t; }" : "=r"(a) : "l"(p));
    return a;
}
static __device__ __forceinline__ void ldm4(uint32_t* r, uint32_t addr) {
    asm volatile("ldmatrix.sync.aligned.m8n8.x4.shared.b16 {%0,%1,%2,%3}, [%4];"
        : "=r"(r[0]), "=r"(r[1]), "=r"(r[2]), "=r"(r[3]) : "r"(addr));
}
static __device__ __forceinline__ void mma16816(float* d, const uint32_t* a, uint32_t b0, uint32_t b1) {
    asm volatile("mma.sync.aligned.m16n8k16.row.col.f32.bf16.bf16.f32 "
        "{%0,%1,%2,%3}, {%4,%5,%6,%7}, {%8,%9}, {%0,%1,%2,%3};"
        : "+f"(d[0]), "+f"(d[1]), "+f"(d[2]), "+f"(d[3])
        : "r"(a[0]), "r"(a[1]), "r"(a[2]), "r"(a[3]), "r"(b0), "r"(b1));
}
static __device__ __forceinline__ void split2(float v, __nv_bfloat16& h, __nv_bfloat16& l) {
    h = __float2bfloat16_rn(v);
    l = __float2bfloat16_rn(v - __bfloat162float(h));
}
static __device__ __forceinline__ uint32_t packbf(__nv_bfloat16 lo, __nv_bfloat16 hi) {
    __nv_bfloat162 t = __halves2bfloat162(lo, hi);
    return *reinterpret_cast<uint32_t*>(&t);
}

// ---------------- spatial GN stats ----------------
__global__ void gn_stats_s(const float* __restrict__ x) {
    int bt = blockIdx.x, g = blockIdx.y;
    int b = bt >> 4, t = bt & 15;
    const float* base = x + ((size_t)(b*512 + g*16))*9216 + (size_t)t*576;
    float s = 0.f, ss = 0.f;
    for (int e = threadIdx.x; e < 9216; e += 256) {
        int cc = e / 576, hw = e - cc*576;
        float v = base[(size_t)cc*9216 + hw];
        s += v; ss += v*v;
    }
    __shared__ float rs[8], rss[8];
    #pragma unroll
    for (int o = 16; o; o >>= 1) {
        s  += __shfl_xor_sync(0xffffffffu, s,  o);
        ss += __shfl_xor_sync(0xffffffffu, ss, o);
    }
    int w = threadIdx.x >> 5;
    if ((threadIdx.x & 31) == 0) { rs[w] = s; rss[w] = ss; }
    __syncthreads();
    if (threadIdx.x == 0) {
        s = 0.f; ss = 0.f;
        #pragma unroll
        for (int i = 0; i < 8; i++) { s += rs[i]; ss += rss[i]; }
        float mean = s * (1.f/9216.f);
        float var  = ss * (1.f/9216.f) - mean*mean;
        g_sts[(bt*32+g)*2+0] = mean;
        g_sts[(bt*32+g)*2+1] = rsqrtf(var + 1e-5f);
    }
}

// --------- normalize + transpose spatial -> hi/lo bf16 token-major ---------
__global__ void norm_tr_s(const float* __restrict__ x,
                          const float* __restrict__ gw, const float* __restrict__ gb) {
    __shared__ float tile[32][33];
    int bt = blockIdx.x, b = bt >> 4, t = bt & 15;
    int hw0 = blockIdx.y*32, c0 = blockIdx.z*32;
    int tx = threadIdx.x, ty = threadIdx.y;
    #pragma unroll
    for (int i = 0; i < 4; i++) {
        int cl = ty + i*8, c = c0 + cl;
        float mean = g_sts[(bt*32 + (c>>4))*2+0];
        float rstd = g_sts[(bt*32 + (c>>4))*2+1];
        float v = x[(((size_t)b*512 + c)*16 + t)*576 + hw0 + tx];
        tile[cl][tx] = (v - mean)*rstd*gw[c] + gb[c];
    }
    __syncthreads();
    #pragma unroll
    for (int i = 0; i < 4; i++) {
        int hwl = ty + i*8;
        size_t o = ((size_t)(bt*576 + hw0 + hwl))*512 + c0 + tx;
        __nv_bfloat16 h, l; split2(tile[tx][hwl], h, l);
        g_Ah[o] = h; g_Al[o] = l;
    }
}

// ---------------- weight split (qkv + proj in one launch) ----------------
__global__ void wsplit2(const float* __restrict__ wq, const float* __restrict__ wp) {
    int i = blockIdx.x*256 + threadIdx.x;
    if (i < 1536*512) {
        __nv_bfloat16 h, l; split2(wq[i], h, l);
        g_Wh[i] = h; g_Wl[i] = l;
    }
    if (i < 512*512) {
        __nv_bfloat16 h, l; split2(wp[i], h, l);
        g_Wh[WOFF + i] = h; g_Wl[WOFF + i] = l;
    }
}

// ---------------- bf16x3 HMMA GEMM (Round-4 config: K-chunk 64, LDG/STS) ----------------
#define SPAD 72
#define GEMM_SMEM 73728
__global__ __launch_bounds__(256) void gemm_mma(
    const __nv_bfloat16* __restrict__ Ah, const __nv_bfloat16* __restrict__ Al,
    const __nv_bfloat16* __restrict__ Bh, const __nv_bfloat16* __restrict__ Bl,
    const float* __restrict__ bias, float* __restrict__ C, int N) {
    extern __shared__ __nv_bfloat16 sm[];
    __nv_bfloat16* sAh = sm;
    __nv_bfloat16* sAl = sm + 9216;
    __nv_bfloat16* sBh = sm + 18432;
    __nv_bfloat16* sBl = sm + 27648;
    int tid = threadIdx.x, wid = tid >> 5, lane = tid & 31;
    int wm = wid >> 2, wn = wid & 3;
    int m0 = blockIdx.y*128, n0 = blockIdx.x*128;
    const __nv_bfloat16* pAh = Ah + (size_t)m0*512;
    const __nv_bfloat16* pAl = Al + (size_t)m0*512;
    const __nv_bfloat16* pBh = Bh + (size_t)n0*512;
    const __nv_bfloat16* pBl = Bl + (size_t)n0*512;

    float acc[4][4][4];
    #pragma unroll
    for (int i = 0; i < 4; i++)
        #pragma unroll
        for (int j = 0; j < 4; j++)
            #pragma unroll
            for (int k = 0; k < 4; k++) acc[i][j][k] = 0.f;

    int lrow = lane & 15, lcol = (lane >> 4) << 3;
    uint32_t aoff = (uint32_t)(( (wm*64 + lrow) * SPAD + lcol ) * 2);
    uint32_t boff = (uint32_t)(( (wn*32 + lrow) * SPAD + lcol ) * 2);
    uint32_t uAh = s2u(sAh) + aoff, uAl = s2u(sAl) + aoff;
    uint32_t uBh = s2u(sBh) + boff, uBl = s2u(sBl) + boff;

    for (int chunk = 0; chunk < 8; chunk++) {
        int koff = chunk*64;
        __syncthreads();
        #pragma unroll
        for (int i = 0; i < 4; i++) {
            int idx = tid + i*256;
            int r = idx >> 3, c8 = (idx & 7) << 3;
            size_t go = (size_t)r*512 + koff + c8;
            int so = r*SPAD + c8;
            *(float4*)(sAh + so) = *(const float4*)(pAh + go);
            *(float4*)(sAl + so) = *(const float4*)(pAl + go);
            *(float4*)(sBh + so) = *(const float4*)(pBh + go);
            *(float4*)(sBl + so) = *(const float4*)(pBl + go);
        }
        __syncthreads();
        #pragma unroll
        for (int k16 = 0; k16 < 4; k16++) {
            uint32_t kb = k16*32;
            uint32_t ah[4][4], al[4][4], bh[2][4], bl[2][4];
            #pragma unroll
            for (int mi = 0; mi < 4; mi++) {
                ldm4(ah[mi], uAh + mi*16*SPAD*2 + kb);
                ldm4(al[mi], uAl + mi*16*SPAD*2 + kb);
            }
            #pragma unroll
            for (int nj = 0; nj < 2; nj++) {
                ldm4(bh[nj], uBh + nj*16*SPAD*2 + kb);
                ldm4(bl[nj], uBl + nj*16*SPAD*2 + kb);
            }
            #pragma unroll
            for (int mi = 0; mi < 4; mi++)
                #pragma unroll
                for (int ni = 0; ni < 4; ni++) {
                    int nj = ni >> 1, hf = ni & 1;
                    mma16816(acc[mi][ni], ah[mi], bh[nj][hf], bh[nj][hf+2]);
                    mma16816(acc[mi][ni], al[mi], bh[nj][hf], bh[nj][hf+2]);
                    mma16816(acc[mi][ni], ah[mi], bl[nj][hf], bl[nj][hf+2]);
                }
        }
    }
    int rbase = m0 + wm*64 + (lane >> 2);
    int cbase = n0 + wn*32 + (lane & 3)*2;
    #pragma unroll
    for (int mi = 0; mi < 4; mi++)
        #pragma unroll
        for (int ni = 0; ni < 4; ni++) {
            int col = cbase + ni*8;
            float2 bv = *(const float2*)(bias + col);
            int r0 = rbase + mi*16;
            float2 o0 = { acc[mi][ni][0] + bv.x, acc[mi][ni][1] + bv.y };
            float2 o1 = { acc[mi][ni][2] + bv.x, acc[mi][ni][3] + bv.y };
            *(float2*)(C + (size_t)r0*N + col) = o0;
            *(float2*)(C + (size_t)(r0+8)*N + col) = o1;
        }
}

// ---- proj_s GEMM with fused residual + transpose-back: x1 = x + C^T  (N=512) ----
__global__ __launch_bounds__(256) void gemm_proj_resid(
    const __nv_bfloat16* __restrict__ Ah, const __nv_bfloat16* __restrict__ Al,
    const __nv_bfloat16* __restrict__ Bh, const __nv_bfloat16* __restrict__ Bl,
    const float* __restrict__ bias, const float* __restrict__ x, float* __restrict__ x1) {
    extern __shared__ __nv_bfloat16 sm[];
    __nv_bfloat16* sAh = sm;
    __nv_bfloat16* sAl = sm + 9216;
    __nv_bfloat16* sBh = sm + 18432;
    __nv_bfloat16* sBl = sm + 27648;
    int tid = threadIdx.x, wid = tid >> 5, lane = tid & 31;
    int wm = wid >> 2, wn = wid & 3;
    int m0 = blockIdx.y*128, n0 = blockIdx.x*128;
    const __nv_bfloat16* pAh = Ah + (size_t)m0*512;
    const __nv_bfloat16* pAl = Al + (size_t)m0*512;
    const __nv_bfloat16* pBh = Bh + (size_t)n0*512;
    const __nv_bfloat16* pBl = Bl + (size_t)n0*512;

    float acc[4][4][4];
    #pragma unroll
    for (int i = 0; i < 4; i++)
        #pragma unroll
        for (int j = 0; j < 4; j++)
            #pragma unroll
            for (int k = 0; k < 4; k++) acc[i][j][k] = 0.f;

    int lrow = lane & 15, lcol = (lane >> 4) << 3;
    uint32_t aoff = (uint32_t)(( (wm*64 + lrow) * SPAD + lcol ) * 2);
    uint32_t boff = (uint32_t)(( (wn*32 + lrow) * SPAD + lcol ) * 2);
    uint32_t uAh = s2u(sAh) + aoff, uAl = s2u(sAl) + aoff;
    uint32_t uBh = s2u(sBh) + boff, uBl = s2u(sBl) + boff;

    for (int chunk = 0; chunk < 8; chunk++) {
        int koff = chunk*64;
        __syncthreads();
        #pragma unroll
        for (int i = 0; i < 4; i++) {
            int idx = tid + i*256;
            int r = idx >> 3, c8 = (idx & 7) << 3;
            size_t go = (size_t)r*512 + koff + c8;
            int so = r*SPAD + c8;
            *(float4*)(sAh + so) = *(const float4*)(pAh + go);
            *(float4*)(sAl + so) = *(const float4*)(pAl + go);
            *(float4*)(sBh + so) = *(const float4*)(pBh + go);
            *(float4*)(sBl + so) = *(const float4*)(pBl + go);
        }
        __syncthreads();
        #pragma unroll
        for (int k16 = 0; k16 < 4; k16++) {
            uint32_t kb = k16*32;
            uint32_t ah[4][4], al[4][4], bh[2][4], bl[2][4];
            #pragma unroll
            for (int mi = 0; mi < 4; mi++) {
                ldm4(ah[mi], uAh + mi*16*SPAD*2 + kb);
                ldm4(al[mi], uAl + mi*16*SPAD*2 + kb);
            }
            #pragma unroll
            for (int nj = 0; nj < 2; nj++) {
                ldm4(bh[nj], uBh + nj*16*SPAD*2 + kb);
                ldm4(bl[nj], uBl + nj*16*SPAD*2 + kb);
            }
            #pragma unroll
            for (int mi = 0; mi < 4; mi++)
                #pragma unroll
                for (int ni = 0; ni < 4; ni++) {
                    int nj = ni >> 1, hf = ni & 1;
                    mma16816(acc[mi][ni], ah[mi], bh[nj][hf], bh[nj][hf+2]);
                    mma16816(acc[mi][ni], al[mi], bh[nj][hf], bh[nj][hf+2]);
                    mma16816(acc[mi][ni], ah[mi], bl[nj][hf], bl[nj][hf+2]);
                }
        }
    }
    // epilogue: stage transposed [c][token] in smem, then coalesced natural writes
    __syncthreads();
    float* ps = (float*)sm;   // 128 c x 132 pad
    {
        int rb = wm*64 + (lane >> 2);
        int cb = wn*32 + (lane & 3)*2;
        #pragma unroll
        for (int mi = 0; mi < 4; mi++)
            #pragma unroll
            for (int ni = 0; ni < 4; ni++) {
                int c = cb + ni*8;
                float2 bv = *(const float2*)(bias + n0 + c);
                int r0 = rb + mi*16;
                ps[c*132 + r0]         = acc[mi][ni][0] + bv.x;
                ps[(c+1)*132 + r0]     = acc[mi][ni][1] + bv.y;
                ps[c*132 + r0 + 8]     = acc[mi][ni][2] + bv.x;
                ps[(c+1)*132 + r0 + 8] = acc[mi][ni][3] + bv.y;
            }
    }
    __syncthreads();
    {
        int w = tid >> 5;
        int r = (tid & 31)*4;
        int tk = m0 + r;
        int ns = tk / 576, hw = tk - ns*576;
        int b = ns >> 4, t = ns & 15;
        #pragma unroll
        for (int i = 0; i < 16; i++) {
            int c = w + i*8;
            float4 v = *(float4*)&ps[c*132 + r];
            size_t o = (((size_t)b*512 + n0 + c)*16 + t)*576 + hw;
            float4 xi = *(const float4*)(x + o);
            v.x += xi.x; v.y += xi.y; v.z += xi.z; v.w += xi.w;
            *(float4*)(x1 + o) = v;
        }
    }
}

// ---------------- spatial flash attention (HMMA bf16x3) ----------------
#define AT_SMEM (6*64*72*2)
__global__ __launch_bounds__(128) void attn_spatial_mma(const float* __restrict__ Y,
        __nv_bfloat16* __restrict__ Oh, __nv_bfloat16* __restrict__ Ol) {
    extern __shared__ __nv_bfloat16 sb[];
    __nv_bfloat16* Qh  = sb;
    __nv_bfloat16* Ql  = sb + 4608;
    __nv_bfloat16* Kh  = sb + 2*4608;
    __nv_bfloat16* Kl  = sb + 3*4608;
    __nv_bfloat16* Vth = sb + 4*4608;
    __nv_bfloat16* Vtl = sb + 5*4608;
    int q0 = blockIdx.x*64, h = blockIdx.y, ns = blockIdx.z;
    int tid = threadIdx.x, wid = tid >> 5, lane = tid & 31;

    {
        int row = tid >> 1, dh = (tid & 1)*32;
        const float* src = Y + ((size_t)(ns*576 + q0 + row))*1536 + h*64 + dh;
        #pragma unroll
        for (int j = 0; j < 8; j++) {
            float4 v = *(const float4*)(src + j*4);
            float vv[4] = {v.x*0.125f, v.y*0.125f, v.z*0.125f, v.w*0.125f};
            #pragma unroll
            for (int e = 0; e < 4; e++) {
                __nv_bfloat16 hh, ll; split2(vv[e], hh, ll);
                Qh[row*72 + dh + j*4 + e] = hh;
                Ql[row*72 + dh + j*4 + e] = ll;
            }
        }
    }
    float oacc[8][4];
    float m[2] = {-1e30f, -1e30f}, l[2] = {0.f, 0.f};
    #pragma unroll
    for (int t = 0; t < 8; t++)
        #pragma unroll
        for (int e = 0; e < 4; e++) oacc[t][e] = 0.f;

    int lrow = lane & 15, lcol = (lane >> 4) << 3;
    uint32_t uQh = s2u(Qh) + ((wid*16 + lrow)*SPAD + lcol)*2;
    uint32_t uQl = s2u(Ql) + ((wid*16 + lrow)*SPAD + lcol)*2;
    uint32_t uKh = s2u(Kh) + (lrow*SPAD + lcol)*2;
    uint32_t uKl = s2u(Kl) + (lrow*SPAD + lcol)*2;
    uint32_t uVh = s2u(Vth) + (lrow*SPAD + lcol)*2;
    uint32_t uVl = s2u(Vtl) + (lrow*SPAD + lcol)*2;

    for (int ch = 0; ch < 9; ch++) {
        __syncthreads();
        {
            int row = tid >> 1, dh = (tid & 1)*32;
            const float* ksrc = Y + ((size_t)(ns*576 + ch*64 + row))*1536 + 512 + h*64 + dh;
            #pragma unroll
            for (int j = 0; j < 8; j++) {
                float4 kv = *(const float4*)(ksrc + j*4);
                float kk[4] = {kv.x, kv.y, kv.z, kv.w};
                float4 vv4 = *(const float4*)(ksrc + 512 + j*4);
                float vvv[4] = {vv4.x, vv4.y, vv4.z, vv4.w};
                #pragma unroll
                for (int e = 0; e < 4; e++) {
                    __nv_bfloat16 hh, ll;
                    split2(kk[e], hh, ll);
                    Kh[row*72 + dh + j*4 + e] = hh;
                    Kl[row*72 + dh + j*4 + e] = ll;
                    split2(vvv[e], hh, ll);
                    Vth[(dh + j*4 + e)*72 + row] = hh;
                    Vtl[(dh + j*4 + e)*72 + row] = ll;
                }
            }
        }
        __syncthreads();
        float sacc[8][4];
        #pragma unroll
        for (int t = 0; t < 8; t++)
            #pragma unroll
            for (int e = 0; e < 4; e++) sacc[t][e] = 0.f;
        #pragma unroll
        for (int k16 = 0; k16 < 4; k16++) {
            uint32_t kb = k16*32;
            uint32_t ah[4], al[4];
            ldm4(ah, uQh + kb);
            ldm4(al, uQl + kb);
            #pragma unroll
            for (int g = 0; g < 4; g++) {
                uint32_t kh[4], kl[4];
                ldm4(kh, uKh + g*16*SPAD*2 + kb);
                ldm4(kl, uKl + g*16*SPAD*2 + kb);
                mma16816(sacc[2*g],   ah, kh[0], kh[2]);
                mma16816(sacc[2*g],   al, kh[0], kh[2]);
                mma16816(sacc[2*g],   ah, kl[0], kl[2]);
                mma16816(sacc[2*g+1], ah, kh[1], kh[3]);
                mma16816(sacc[2*g+1], al, kh[1], kh[3]);
                mma16816(sacc[2*g+1], ah, kl[1], kl[3]);
            }
        }
        uint32_t phx[8][2], plx[8][2];
        #pragma unroll
        for (int hf = 0; hf < 2; hf++) {
            float mx = -1e30f;
            #pragma unroll
            for (int t = 0; t < 8; t++)
                mx = fmaxf(mx, fmaxf(sacc[t][2*hf], sacc[t][2*hf+1]));
            mx = fmaxf(mx, __shfl_xor_sync(0xffffffffu, mx, 1));
            mx = fmaxf(mx, __shfl_xor_sync(0xffffffffu, mx, 2));
            float nm = fmaxf(m[hf], mx);
            float alpha = __expf(m[hf] - nm);
            float rs = 0.f;
            #pragma unroll
            for (int t = 0; t < 8; t++) {
                float p0 = __expf(sacc[t][2*hf]   - nm);
                float p1 = __expf(sacc[t][2*hf+1] - nm);
                rs += p0 + p1;
                __nv_bfloat16 h0, l0, h1, l1;
                split2(p0, h0, l0); split2(p1, h1, l1);
                phx[t][hf] = packbf(h0, h1);
                plx[t][hf] = packbf(l0, l1);
            }
            rs += __shfl_xor_sync(0xffffffffu, rs, 1);
            rs += __shfl_xor_sync(0xffffffffu, rs, 2);
            l[hf] = l[hf]*alpha + rs;
            m[hf] = nm;
            #pragma unroll
            for (int t = 0; t < 8; t++) {
                oacc[t][2*hf]   *= alpha;
                oacc[t][2*hf+1] *= alpha;
            }
        }
        #pragma unroll
        for (int g = 0; g < 4; g++) {
            uint32_t pah[4] = {phx[2*g][0], phx[2*g][1], phx[2*g+1][0], phx[2*g+1][1]};
            uint32_t pal[4] = {plx[2*g][0], plx[2*g][1], plx[2*g+1][0], plx[2*g+1][1]};
            #pragma unroll
            for (int dt = 0; dt < 4; dt++) {
                uint32_t vh[4], vl[4];
                ldm4(vh, uVh + dt*16*SPAD*2 + g*32);
                ldm4(vl, uVl + dt*16*SPAD*2 + g*32);
                mma16816(oacc[2*dt],   pah, vh[0], vh[2]);
                mma16816(oacc[2*dt],   pal, vh[0], vh[2]);
                mma16816(oacc[2*dt],   pah, vl[0], vl[2]);
                mma16816(oacc[2*dt+1], pah, vh[1], vh[3]);
                mma16816(oacc[2*dt+1], pal, vh[1], vh[3]);
                mma16816(oacc[2*dt+1], pah, vl[1], vl[3]);
            }
        }
    }
    float inv0 = 1.f / l[0], inv1 = 1.f / l[1];
    int r0 = q0 + wid*16 + (lane >> 2);
    int col0 = h*64 + (lane & 3)*2;
    #pragma unroll
    for (int t = 0; t < 8; t++) {
        int col = col0 + t*8;
        __nv_bfloat16 h0, l0h, h1, l1h;
        split2(oacc[t][0]*inv0, h0, l0h);
        split2(oacc[t][1]*inv0, h1, l1h);
        size_t offA = ((size_t)(ns*576 + r0))*512 + col;
        *(__nv_bfloat162*)(Oh + offA) = __halves2bfloat162(h0, h1);
        *(__nv_bfloat162*)(Ol + offA) = __halves2bfloat162(l0h, l1h);
        split2(oacc[t][2]*inv1, h0, l0h);
        split2(oacc[t][3]*inv1, h1, l1h);
        size_t offB = ((size_t)(ns*576 + r0 + 8))*512 + col;
        *(__nv_bfloat162*)(Oh + offB) = __halves2bfloat162(h0, h1);
        *(__nv_bfloat162*)(Ol + offB) = __halves2bfloat162(l0h, l1h);
    }
}

// ---------------- temporal GN stats (more blocks) ----------------
__global__ void gn_stats_t() {
    int b = blockIdx.x, g = blockIdx.y, hw = blockIdx.z*64 + threadIdx.x;
    const float* base = g_x1 + ((size_t)b*512 + g*16)*9216 + hw;
    float s = 0.f, ss = 0.f;
    for (int cc = 0; cc < 16; cc++)
        #pragma unroll
        for (int t = 0; t < 16; t++) {
            float v = base[(size_t)cc*9216 + t*576];
            s += v; ss += v*v;
        }
    float mean = s*(1.f/256.f);
    float var  = ss*(1.f/256.f) - mean*mean;
    g_stt[((size_t)(b*576+hw)*32 + g)*2 + 0] = mean;
    g_stt[((size_t)(b*576+hw)*32 + g)*2 + 1] = rsqrtf(var + 1e-5f);
}

// --------- normalize + transpose temporal -> hi/lo bf16 token-major ---------
__global__ void norm_tr_t(const float* __restrict__ gw, const float* __restrict__ gb) {
    __shared__ float tile[32][33];
    int bt = blockIdx.x, b = bt >> 4, t = bt & 15;
    int hw0 = blockIdx.y*32, c0 = blockIdx.z*32;
    int tx = threadIdx.x, ty = threadIdx.y;
    #pragma unroll
    for (int i = 0; i < 4; i++) {
        int cl = ty + i*8, c = c0 + cl, hw = hw0 + tx;
        float mean = g_stt[((size_t)(b*576+hw)*32 + (c>>4))*2 + 0];
        float rstd = g_stt[((size_t)(b*576+hw)*32 + (c>>4))*2 + 1];
        float v = g_x1[(((size_t)b*512 + c)*16 + t)*576 + hw];
        tile[cl][tx] = (v - mean)*rstd*gw[c] + gb[c];
    }
    __syncthreads();
    #pragma unroll
    for (int i = 0; i < 4; i++) {
        int hwl = ty + i*8;
        size_t o = ((size_t)((b*576 + hw0 + hwl)*16 + t))*512 + c0 + tx;
        __nv_bfloat16 h, l; split2(tile[tx][hwl], h, l);
        g_Ah[o] = h; g_Al[o] = l;
    }
}

// ---------------- temporal attention ----------------
__global__ __launch_bounds__(256) void attn_temporal(const float* __restrict__ Y,
    const float* __restrict__ rpk, const float* __restrict__ rpv,
    __nv_bfloat16* __restrict__ Oh, __nv_bfloat16* __restrict__ Ol) {
    __shared__ float qs[16][68], ks[16][68], vs[16][68];
    __shared__ float pk[33][68], pvt[33][68], wsm[16][20];
    int h = blockIdx.x, samp = blockIdx.y, tid = threadIdx.x;
    for (int i = tid; i < 33*64; i += 256) {
        pk [i>>6][i&63] = rpk[i];
        pvt[i>>6][i&63] = rpv[i];
    }
    {
        int t = tid >> 4, d0 = (tid & 15)*4;
        const float* base = Y + ((size_t)(samp*16 + t))*1536 + h*64 + d0;
        float4 q4 = *(const float4*)(base);
        float4 k4 = *(const float4*)(base + 512);
        float4 v4 = *(const float4*)(base + 1024);
        qs[t][d0+0]=q4.x; qs[t][d0+1]=q4.y; qs[t][d0+2]=q4.z; qs[t][d0+3]=q4.w;
        ks[t][d0+0]=k4.x; ks[t][d0+1]=k4.y; ks[t][d0+2]=k4.z; ks[t][d0+3]=k4.w;
        vs[t][d0+0]=v4.x; vs[t][d0+1]=v4.y; vs[t][d0+2]=v4.z; vs[t][d0+3]=v4.w;
    }
    __syncthreads();
    {
        int t = tid >> 4, s = tid & 15;
        float wv = -1e30f;
        if (s <= t) {
            float a = 0.f, bb = 0.f;
            int ri = t - s + 16;
            for (int d = 0; d < 64; d++) {
                a  += qs[t][d]*ks[s][d];
                bb += qs[s][d]*pk[ri][d];
            }
            wv = 0.125f*a + SCALE*bb;
        }
        float mx = wv;
        #pragma unroll
        for (int o = 8; o; o >>= 1) mx = fmaxf(mx, __shfl_xor_sync(0xffffffffu, mx, o, 16));
        float e = (s <= t) ? __expf(wv - mx) : 0.f;
        float sum = e;
        #pragma unroll
        for (int o = 8; o; o >>= 1) sum += __shfl_xor_sync(0xffffffffu, sum, o, 16);
        wsm[t][s] = e / sum;
    }
    __syncthreads();
    {
        int t = tid >> 4, d0 = (tid & 15)*4;
        float o0 = 0.f, o1 = 0.f, o2 = 0.f, o3 = 0.f;
        #pragma unroll
        for (int s = 0; s < 16; s++) {
            float p = wsm[t][s];
            int ri = s - t + 16;
            o0 += p*(vs[s][d0+0] + pvt[ri][d0+0]);
            o1 += p*(vs[s][d0+1] + pvt[ri][d0+1]);
            o2 += p*(vs[s][d0+2] + pvt[ri][d0+2]);
            o3 += p*(vs[s][d0+3] + pvt[ri][d0+3]);
        }
        size_t off = ((size_t)(samp*16 + t))*512 + h*64 + d0;
        __nv_bfloat16 h0, l0, h1, l1, h2, l2, h3, l3;
        split2(o0, h0, l0); split2(o1, h1, l1);
        split2(o2, h2, l2); split2(o3, h3, l3);
        *(__nv_bfloat162*)(Oh + off)     = __halves2bfloat162(h0, h1);
        *(__nv_bfloat162*)(Oh + off + 2) = __halves2bfloat162(h2, h3);
        *(__nv_bfloat162*)(Ol + off)     = __halves2bfloat162(l0, l1);
        *(__nv_bfloat162*)(Ol + off + 2) = __halves2bfloat162(l2, l3);
    }
}

// --------- final add (temporal) ---------
__global__ void final_add(float* __restrict__ out) {
    __shared__ float tile[32][33];
    int bt = blockIdx.x, b = bt >> 4, t = bt & 15;
    int hw0 = blockIdx.y*32, c0 = blockIdx.z*32;
    int tx = threadIdx.x, ty = threadIdx.y;
    #pragma unroll
    for (int i = 0; i < 4; i++) {
        int hwl = ty + i*8;
        tile[tx][hwl] = g_P[((size_t)((b*576 + hw0 + hwl)*16 + t))*512 + c0 + tx];
    }
    __syncthreads();
    #pragma unroll
    for (int i = 0; i < 4; i++) {
        int cl = ty + i*8;
        size_t idx = (((size_t)b*512 + c0 + cl)*16 + t)*576 + hw0 + tx;
        out[idx] = g_x1[idx] + tile[cl][tx];
    }
}

extern "C" void kernel_launch(void* const* d_in, const int* in_sizes, int n_in,
                              void* d_out, int out_size) {
    const float* x        = (const float*)d_in[0];
    const float* norm_s_w = (const float*)d_in[1];
    const float* norm_s_b = (const float*)d_in[2];
    const float* qkv_s_w  = (const float*)d_in[3];
    const float* qkv_s_b  = (const float*)d_in[4];
    const float* proj_s_w = (const float*)d_in[5];
    const float* proj_s_b = (const float*)d_in[6];
    const float* norm_t_w = (const float*)d_in[7];
    const float* norm_t_b = (const float*)d_in[8];
    const float* qkv_t_w  = (const float*)d_in[9];
    const float* qkv_t_b  = (const float*)d_in[10];
    const float* proj_t_w = (const float*)d_in[11];
    const float* proj_t_b = (const float*)d_in[12];
    const float* rpk      = (const float*)d_in[13];
    const float* rpv      = (const float*)d_in[14];
    float* out = (float*)d_out;

    float *gY, *gP, *gX1;
    __nv_bfloat16 *gAh, *gAl, *gWh, *gWl;
    cudaGetSymbolAddress((void**)&gY,  g_Y);
    cudaGetSymbolAddress((void**)&gP,  g_P);
    cudaGetSymbolAddress((void**)&gX1, g_x1);
    cudaGetSymbolAddress((void**)&gAh, g_Ah);
    cudaGetSymbolAddress((void**)&gAl, g_Al);
    cudaGetSymbolAddress((void**)&gWh, g_Wh);
    cudaGetSymbolAddress((void**)&gWl, g_Wl);

    cudaFuncSetAttribute(gemm_mma, cudaFuncAttributeMaxDynamicSharedMemorySize, GEMM_SMEM);
    cudaFuncSetAttribute(gemm_proj_resid, cudaFuncAttributeMaxDynamicSharedMemorySize, GEMM_SMEM);
    cudaFuncSetAttribute(attn_spatial_mma, cudaFuncAttributeMaxDynamicSharedMemorySize, AT_SMEM);

    dim3 tb(32, 8);
    dim3 tg(32, 18, 16);

    // spatial branch
    gn_stats_s<<<dim3(32,32), 256>>>(x);
    norm_tr_s<<<tg, tb>>>(x, norm_s_w, norm_s_b);
    wsplit2<<<3072, 256>>>(qkv_s_w, proj_s_w);
    gemm_mma<<<dim3(12,144), 256, GEMM_SMEM>>>(gAh, gAl, gWh, gWl, qkv_s_b, gY, 1536);
    attn_spatial_mma<<<dim3(9,8,32), 128, AT_SMEM>>>(gY, gAh, gAl);
    gemm_proj_resid<<<dim3(4,144), 256, GEMM_SMEM>>>(gAh, gAl, gWh + WOFF, gWl + WOFF,
                                                     proj_s_b, x, gX1);
    // temporal branch
    gn_stats_t<<<dim3(2,32,9), 64>>>();
    norm_tr_t<<<tg, tb>>>(norm_t_w, norm_t_b);
    wsplit2<<<3072, 256>>>(qkv_t_w, proj_t_w);
    gemm_mma<<<dim3(12,144), 256, GEMM_SMEM>>>(gAh, gAl, gWh, gWl, qkv_t_b, gY, 1536);
    attn_temporal<<<dim3(8,1152), 256>>>(gY, rpk, rpv, gAh, gAl);
    gemm_mma<<<dim3(4,144), 256, GEMM_SMEM>>>(gAh, gAl, gWh + WOFF, gWl + WOFF, proj_t_b, gP, 512);
    final_add<<<tg, tb>>>(out);
}

// round 8
// speedup vs baseline: 2.0118x; 1.1005x over previous
#include <cuda_runtime.h>
#include <cuda_bf16.h>
#include <stdint.h>
#include <math.h>

#define TOK 18432
#define SCALE 0.35355339059327373f
#define WOFF (1536*512)

static __device__ float g_Y [TOK*1536];
static __device__ float g_x1[TOK*512];
static __device__ __nv_bfloat16 g_Ah[TOK*512];
static __device__ __nv_bfloat16 g_Al[TOK*512];
static __device__ __nv_bfloat16 g_Wh[2048*512];
static __device__ __nv_bfloat16 g_Wl[2048*512];
static __device__ float g_sts[32*32*2];
static __device__ float g_stt[1152*32*2];

static __device__ __forceinline__ uint32_t s2u(const void* p) {
    uint32_t a;
    asm("{ .reg .u64 t; cvta.to.shared.u64 t, %1; cvt.u32.u64 %0, t; }" : "=r"(a) : "l"(p));
    return a;
}
static __device__ __forceinline__ void ldm4(uint32_t* r, uint32_t addr) {
    asm volatile("ldmatrix.sync.aligned.m8n8.x4.shared.b16 {%0,%1,%2,%3}, [%4];"
        : "=r"(r[0]), "=r"(r[1]), "=r"(r[2]), "=r"(r[3]) : "r"(addr));
}
static __device__ __forceinline__ void ldm4t(uint32_t* r, uint32_t addr) {
    asm volatile("ldmatrix.sync.aligned.m8n8.x4.trans.shared.b16 {%0,%1,%2,%3}, [%4];"
        : "=r"(r[0]), "=r"(r[1]), "=r"(r[2]), "=r"(r[3]) : "r"(addr));
}
static __device__ __forceinline__ void mma16816(float* d, const uint32_t* a, uint32_t b0, uint32_t b1) {
    asm volatile("mma.sync.aligned.m16n8k16.row.col.f32.bf16.bf16.f32 "
        "{%0,%1,%2,%3}, {%4,%5,%6,%7}, {%8,%9}, {%0,%1,%2,%3};"
        : "+f"(d[0]), "+f"(d[1]), "+f"(d[2]), "+f"(d[3])
        : "r"(a[0]), "r"(a[1]), "r"(a[2]), "r"(a[3]), "r"(b0), "r"(b1));
}
static __device__ __forceinline__ void split2(float v, __nv_bfloat16& h, __nv_bfloat16& l) {
    h = __float2bfloat16_rn(v);
    l = __float2bfloat16_rn(v - __bfloat162float(h));
}
static __device__ __forceinline__ uint32_t packbf(__nv_bfloat16 lo, __nv_bfloat16 hi) {
    __nv_bfloat162 t = __halves2bfloat162(lo, hi);
    return *reinterpret_cast<uint32_t*>(&t);
}

// ---------------- spatial GN stats ----------------
__global__ void gn_stats_s(const float* __restrict__ x) {
    int bt = blockIdx.x, g = blockIdx.y;
    int b = bt >> 4, t = bt & 15;
    const float* base = x + ((size_t)(b*512 + g*16))*9216 + (size_t)t*576;
    float s = 0.f, ss = 0.f;
    for (int e = threadIdx.x; e < 9216; e += 256) {
        int cc = e / 576, hw = e - cc*576;
        float v = base[(size_t)cc*9216 + hw];
        s += v; ss += v*v;
    }
    __shared__ float rs[8], rss[8];
    #pragma unroll
    for (int o = 16; o; o >>= 1) {
        s  += __shfl_xor_sync(0xffffffffu, s,  o);
        ss += __shfl_xor_sync(0xffffffffu, ss, o);
    }
    int w = threadIdx.x >> 5;
    if ((threadIdx.x & 31) == 0) { rs[w] = s; rss[w] = ss; }
    __syncthreads();
    if (threadIdx.x == 0) {
        s = 0.f; ss = 0.f;
        #pragma unroll
        for (int i = 0; i < 8; i++) { s += rs[i]; ss += rss[i]; }
        float mean = s * (1.f/9216.f);
        float var  = ss * (1.f/9216.f) - mean*mean;
        g_sts[(bt*32+g)*2+0] = mean;
        g_sts[(bt*32+g)*2+1] = rsqrtf(var + 1e-5f);
    }
}

// --------- normalize + transpose spatial -> hi/lo bf16 token-major ---------
__global__ void norm_tr_s(const float* __restrict__ x,
                          const float* __restrict__ gw, const float* __restrict__ gb) {
    __shared__ float tile[32][33];
    int bt = blockIdx.x, b = bt >> 4, t = bt & 15;
    int hw0 = blockIdx.y*32, c0 = blockIdx.z*32;
    int tx = threadIdx.x, ty = threadIdx.y;
    #pragma unroll
    for (int i = 0; i < 4; i++) {
        int cl = ty + i*8, c = c0 + cl;
        float mean = g_sts[(bt*32 + (c>>4))*2+0];
        float rstd = g_sts[(bt*32 + (c>>4))*2+1];
        float v = x[(((size_t)b*512 + c)*16 + t)*576 + hw0 + tx];
        tile[cl][tx] = (v - mean)*rstd*gw[c] + gb[c];
    }
    __syncthreads();
    #pragma unroll
    for (int i = 0; i < 4; i++) {
        int hwl = ty + i*8;
        size_t o = ((size_t)(bt*576 + hw0 + hwl))*512 + c0 + tx;
        __nv_bfloat16 h, l; split2(tile[tx][hwl], h, l);
        g_Ah[o] = h; g_Al[o] = l;
    }
}

// ---------------- weight split (qkv + proj in one launch) ----------------
__global__ void wsplit2(const float* __restrict__ wq, const float* __restrict__ wp) {
    int i = blockIdx.x*256 + threadIdx.x;
    if (i < 1536*512) {
        __nv_bfloat16 h, l; split2(wq[i], h, l);
        g_Wh[i] = h; g_Wl[i] = l;
    }
    if (i < 512*512) {
        __nv_bfloat16 h, l; split2(wp[i], h, l);
        g_Wh[WOFF + i] = h; g_Wl[WOFF + i] = l;
    }
}

// ---------------- bf16x3 HMMA GEMM (K-chunk 64, LDG/STS) ----------------
#define SPAD 72
#define GEMM_SMEM 73728
__global__ __launch_bounds__(256) void gemm_mma(
    const __nv_bfloat16* __restrict__ Ah, const __nv_bfloat16* __restrict__ Al,
    const __nv_bfloat16* __restrict__ Bh, const __nv_bfloat16* __restrict__ Bl,
    const float* __restrict__ bias, float* __restrict__ C, int N) {
    extern __shared__ __nv_bfloat16 sm[];
    __nv_bfloat16* sAh = sm;
    __nv_bfloat16* sAl = sm + 9216;
    __nv_bfloat16* sBh = sm + 18432;
    __nv_bfloat16* sBl = sm + 27648;
    int tid = threadIdx.x, wid = tid >> 5, lane = tid & 31;
    int wm = wid >> 2, wn = wid & 3;
    int m0 = blockIdx.y*128, n0 = blockIdx.x*128;
    const __nv_bfloat16* pAh = Ah + (size_t)m0*512;
    const __nv_bfloat16* pAl = Al + (size_t)m0*512;
    const __nv_bfloat16* pBh = Bh + (size_t)n0*512;
    const __nv_bfloat16* pBl = Bl + (size_t)n0*512;

    float acc[4][4][4];
    #pragma unroll
    for (int i = 0; i < 4; i++)
        #pragma unroll
        for (int j = 0; j < 4; j++)
            #pragma unroll
            for (int k = 0; k < 4; k++) acc[i][j][k] = 0.f;

    int lrow = lane & 15, lcol = (lane >> 4) << 3;
    uint32_t aoff = (uint32_t)(( (wm*64 + lrow) * SPAD + lcol ) * 2);
    uint32_t boff = (uint32_t)(( (wn*32 + lrow) * SPAD + lcol ) * 2);
    uint32_t uAh = s2u(sAh) + aoff, uAl = s2u(sAl) + aoff;
    uint32_t uBh = s2u(sBh) + boff, uBl = s2u(sBl) + boff;

    for (int chunk = 0; chunk < 8; chunk++) {
        int koff = chunk*64;
        __syncthreads();
        #pragma unroll
        for (int i = 0; i < 4; i++) {
            int idx = tid + i*256;
            int r = idx >> 3, c8 = (idx & 7) << 3;
            size_t go = (size_t)r*512 + koff + c8;
            int so = r*SPAD + c8;
            *(float4*)(sAh + so) = *(const float4*)(pAh + go);
            *(float4*)(sAl + so) = *(const float4*)(pAl + go);
            *(float4*)(sBh + so) = *(const float4*)(pBh + go);
            *(float4*)(sBl + so) = *(const float4*)(pBl + go);
        }
        __syncthreads();
        #pragma unroll
        for (int k16 = 0; k16 < 4; k16++) {
            uint32_t kb = k16*32;
            uint32_t ah[4][4], al[4][4], bh[2][4], bl[2][4];
            #pragma unroll
            for (int mi = 0; mi < 4; mi++) {
                ldm4(ah[mi], uAh + mi*16*SPAD*2 + kb);
                ldm4(al[mi], uAl + mi*16*SPAD*2 + kb);
            }
            #pragma unroll
            for (int nj = 0; nj < 2; nj++) {
                ldm4(bh[nj], uBh + nj*16*SPAD*2 + kb);
                ldm4(bl[nj], uBl + nj*16*SPAD*2 + kb);
            }
            #pragma unroll
            for (int mi = 0; mi < 4; mi++)
                #pragma unroll
                for (int ni = 0; ni < 4; ni++) {
                    int nj = ni >> 1, hf = ni & 1;
                    mma16816(acc[mi][ni], ah[mi], bh[nj][hf], bh[nj][hf+2]);
                    mma16816(acc[mi][ni], al[mi], bh[nj][hf], bh[nj][hf+2]);
                    mma16816(acc[mi][ni], ah[mi], bl[nj][hf], bl[nj][hf+2]);
                }
        }
    }
    int rbase = m0 + wm*64 + (lane >> 2);
    int cbase = n0 + wn*32 + (lane & 3)*2;
    #pragma unroll
    for (int mi = 0; mi < 4; mi++)
        #pragma unroll
        for (int ni = 0; ni < 4; ni++) {
            int col = cbase + ni*8;
            float2 bv = *(const float2*)(bias + col);
            int r0 = rbase + mi*16;
            float2 o0 = { acc[mi][ni][0] + bv.x, acc[mi][ni][1] + bv.y };
            float2 o1 = { acc[mi][ni][2] + bv.x, acc[mi][ni][3] + bv.y };
            *(float2*)(C + (size_t)r0*N + col) = o0;
            *(float2*)(C + (size_t)(r0+8)*N + col) = o1;
        }
}

// ---- shared GEMM mainloop macro body for the two fused-residual variants ----
#define GEMM_BODY()                                                              \
    float acc[4][4][4];                                                          \
    _Pragma("unroll")                                                            \
    for (int i = 0; i < 4; i++)                                                  \
        _Pragma("unroll")                                                        \
        for (int j = 0; j < 4; j++)                                              \
            _Pragma("unroll")                                                    \
            for (int k = 0; k < 4; k++) acc[i][j][k] = 0.f;                      \
    int lrow = lane & 15, lcol = (lane >> 4) << 3;                               \
    uint32_t aoff = (uint32_t)(( (wm*64 + lrow) * SPAD + lcol ) * 2);            \
    uint32_t boff = (uint32_t)(( (wn*32 + lrow) * SPAD + lcol ) * 2);            \
    uint32_t uAh = s2u(sAh) + aoff, uAl = s2u(sAl) + aoff;                       \
    uint32_t uBh = s2u(sBh) + boff, uBl = s2u(sBl) + boff;                       \
    for (int chunk = 0; chunk < 8; chunk++) {                                    \
        int koff = chunk*64;                                                     \
        __syncthreads();                                                         \
        _Pragma("unroll")                                                        \
        for (int i = 0; i < 4; i++) {                                            \
            int idx = tid + i*256;                                               \
            int r = idx >> 3, c8 = (idx & 7) << 3;                               \
            size_t go = (size_t)r*512 + koff + c8;                               \
            int so = r*SPAD + c8;                                                \
            *(float4*)(sAh + so) = *(const float4*)(pAh + go);                   \
            *(float4*)(sAl + so) = *(const float4*)(pAl + go);                   \
            *(float4*)(sBh + so) = *(const float4*)(pBh + go);                   \
            *(float4*)(sBl + so) = *(const float4*)(pBl + go);                   \
        }                                                                        \
        __syncthreads();                                                         \
        _Pragma("unroll")                                                        \
        for (int k16 = 0; k16 < 4; k16++) {                                      \
            uint32_t kb = k16*32;                                                \
            uint32_t ah[4][4], al[4][4], bh[2][4], bl[2][4];                     \
            _Pragma("unroll")                                                    \
            for (int mi = 0; mi < 4; mi++) {                                     \
                ldm4(ah[mi], uAh + mi*16*SPAD*2 + kb);                           \
                ldm4(al[mi], uAl + mi*16*SPAD*2 + kb);                           \
            }                                                                    \
            _Pragma("unroll")                                                    \
            for (int nj = 0; nj < 2; nj++) {                                     \
                ldm4(bh[nj], uBh + nj*16*SPAD*2 + kb);                           \
                ldm4(bl[nj], uBl + nj*16*SPAD*2 + kb);                           \
            }                                                                    \
            _Pragma("unroll")                                                    \
            for (int mi = 0; mi < 4; mi++)                                       \
                _Pragma("unroll")                                                \
                for (int ni = 0; ni < 4; ni++) {                                 \
                    int nj = ni >> 1, hf = ni & 1;                               \
                    mma16816(acc[mi][ni], ah[mi], bh[nj][hf], bh[nj][hf+2]);     \
                    mma16816(acc[mi][ni], al[mi], bh[nj][hf], bh[nj][hf+2]);     \
                    mma16816(acc[mi][ni], ah[mi], bl[nj][hf], bl[nj][hf+2]);     \
                }                                                                \
        }                                                                        \
    }                                                                            \
    __syncthreads();                                                             \
    float* ps = (float*)sm;                                                      \
    {                                                                            \
        int rb = wm*64 + (lane >> 2);                                            \
        int cb = wn*32 + (lane & 3)*2;                                           \
        _Pragma("unroll")                                                        \
        for (int mi = 0; mi < 4; mi++)                                           \
            _Pragma("unroll")                                                    \
            for (int ni = 0; ni < 4; ni++) {                                     \
                int c = cb + ni*8;                                               \
                float2 bv = *(const float2*)(bias + n0 + c);                     \
                int r0 = rb + mi*16;                                             \
                ps[c*132 + r0]         = acc[mi][ni][0] + bv.x;                  \
                ps[(c+1)*132 + r0]     = acc[mi][ni][1] + bv.y;                  \
                ps[c*132 + r0 + 8]     = acc[mi][ni][2] + bv.x;                  \
                ps[(c+1)*132 + r0 + 8] = acc[mi][ni][3] + bv.y;                  \
            }                                                                    \
    }                                                                            \
    __syncthreads();

// ---- proj_s GEMM + fused spatial residual: x1 = x + C^T ----
__global__ __launch_bounds__(256) void gemm_proj_resid(
    const __nv_bfloat16* __restrict__ Ah, const __nv_bfloat16* __restrict__ Al,
    const __nv_bfloat16* __restrict__ Bh, const __nv_bfloat16* __restrict__ Bl,
    const float* __restrict__ bias, const float* __restrict__ x, float* __restrict__ x1) {
    extern __shared__ __nv_bfloat16 sm[];
    __nv_bfloat16* sAh = sm;
    __nv_bfloat16* sAl = sm + 9216;
    __nv_bfloat16* sBh = sm + 18432;
    __nv_bfloat16* sBl = sm + 27648;
    int tid = threadIdx.x, wid = tid >> 5, lane = tid & 31;
    int wm = wid >> 2, wn = wid & 3;
    int m0 = blockIdx.y*128, n0 = blockIdx.x*128;
    const __nv_bfloat16* pAh = Ah + (size_t)m0*512;
    const __nv_bfloat16* pAl = Al + (size_t)m0*512;
    const __nv_bfloat16* pBh = Bh + (size_t)n0*512;
    const __nv_bfloat16* pBl = Bl + (size_t)n0*512;
    GEMM_BODY()
    {
        int w = tid >> 5;
        int r = (tid & 31)*4;
        int tk = m0 + r;
        int ns = tk / 576, hw = tk - ns*576;
        int b = ns >> 4, t = ns & 15;
        #pragma unroll
        for (int i = 0; i < 16; i++) {
            int c = w + i*8;
            float4 v = *(float4*)&ps[c*132 + r];
            size_t o = (((size_t)b*512 + n0 + c)*16 + t)*576 + hw;
            float4 xi = *(const float4*)(x + o);
            v.x += xi.x; v.y += xi.y; v.z += xi.z; v.w += xi.w;
            *(float4*)(x1 + o) = v;
        }
    }
}

// ---- proj_t GEMM + fused temporal residual: out = x1 + C^T (temporal token map) ----
__global__ __launch_bounds__(256) void gemm_proj_resid_t(
    const __nv_bfloat16* __restrict__ Ah, const __nv_bfloat16* __restrict__ Al,
    const __nv_bfloat16* __restrict__ Bh, const __nv_bfloat16* __restrict__ Bl,
    const float* __restrict__ bias, const float* __restrict__ xr, float* __restrict__ outp) {
    extern __shared__ __nv_bfloat16 sm[];
    __nv_bfloat16* sAh = sm;
    __nv_bfloat16* sAl = sm + 9216;
    __nv_bfloat16* sBh = sm + 18432;
    __nv_bfloat16* sBl = sm + 27648;
    int tid = threadIdx.x, wid = tid >> 5, lane = tid & 31;
    int wm = wid >> 2, wn = wid & 3;
    int m0 = blockIdx.y*128, n0 = blockIdx.x*128;
    const __nv_bfloat16* pAh = Ah + (size_t)m0*512;
    const __nv_bfloat16* pAl = Al + (size_t)m0*512;
    const __nv_bfloat16* pBh = Bh + (size_t)n0*512;
    const __nv_bfloat16* pBl = Bl + (size_t)n0*512;
    GEMM_BODY()
    {
        // token tk = (b*576+hw)*16 + t; tile = 8 hw values x 16 t
        int ns2 = m0 >> 4;                 // b*576 + hw0
        int b = ns2 / 576, hw0 = ns2 - b*576;
        int t = tid & 15;
        #pragma unroll
        for (int it = 0; it < 8; it++) {
            int c = it*16 + (tid >> 4);
            float v[8];
            #pragma unroll
            for (int hwl = 0; hwl < 8; hwl++)
                v[hwl] = ps[c*132 + hwl*16 + t];
            size_t o = (((size_t)b*512 + n0 + c)*16 + t)*576 + hw0;
            float4 x0 = *(const float4*)(xr + o);
            float4 x1v = *(const float4*)(xr + o + 4);
            float4 o0 = { v[0]+x0.x, v[1]+x0.y, v[2]+x0.z, v[3]+x0.w };
            float4 o1 = { v[4]+x1v.x, v[5]+x1v.y, v[6]+x1v.z, v[7]+x1v.w };
            *(float4*)(outp + o)     = o0;
            *(float4*)(outp + o + 4) = o1;
        }
    }
}

// ---------------- spatial flash attention (HMMA bf16x3, V natural + ldmatrix.trans) ----------------
#define AT_SMEM (6*64*72*2)
__global__ __launch_bounds__(128) void attn_spatial_mma(const float* __restrict__ Y,
        __nv_bfloat16* __restrict__ Oh, __nv_bfloat16* __restrict__ Ol) {
    extern __shared__ __nv_bfloat16 sb[];
    __nv_bfloat16* Qh = sb;
    __nv_bfloat16* Ql = sb + 4608;
    __nv_bfloat16* Kh = sb + 2*4608;
    __nv_bfloat16* Kl = sb + 3*4608;
    __nv_bfloat16* Vh = sb + 4*4608;
    __nv_bfloat16* Vl = sb + 5*4608;
    int q0 = blockIdx.x*64, h = blockIdx.y, ns = blockIdx.z;
    int tid = threadIdx.x, wid = tid >> 5, lane = tid & 31;

    {   // load Q once, fold 0.125, split hi/lo, packed 8B stores
        int row = tid >> 1, dh = (tid & 1)*32;
        const float* src = Y + ((size_t)(ns*576 + q0 + row))*1536 + h*64 + dh;
        #pragma unroll
        for (int j = 0; j < 8; j++) {
            float4 v = *(const float4*)(src + j*4);
            float vv[4] = {v.x*0.125f, v.y*0.125f, v.z*0.125f, v.w*0.125f};
            __nv_bfloat16 hh[4], ll[4];
            #pragma unroll
            for (int e = 0; e < 4; e++) split2(vv[e], hh[e], ll[e]);
            uint2 uh = { packbf(hh[0],hh[1]), packbf(hh[2],hh[3]) };
            uint2 ul = { packbf(ll[0],ll[1]), packbf(ll[2],ll[3]) };
            *(uint2*)(Qh + row*72 + dh + j*4) = uh;
            *(uint2*)(Ql + row*72 + dh + j*4) = ul;
        }
    }
    float oacc[8][4];
    float m[2] = {-1e30f, -1e30f}, l[2] = {0.f, 0.f};
    #pragma unroll
    for (int t = 0; t < 8; t++)
        #pragma unroll
        for (int e = 0; e < 4; e++) oacc[t][e] = 0.f;

    int lrow = lane & 15, lcol = (lane >> 4) << 3;
    uint32_t uQh = s2u(Qh) + ((wid*16 + lrow)*SPAD + lcol)*2;
    uint32_t uQl = s2u(Ql) + ((wid*16 + lrow)*SPAD + lcol)*2;
    uint32_t uKh = s2u(Kh) + (lrow*SPAD + lcol)*2;
    uint32_t uKl = s2u(Kl) + (lrow*SPAD + lcol)*2;
    uint32_t uVh = s2u(Vh) + (lrow*SPAD + lcol)*2;
    uint32_t uVl = s2u(Vl) + (lrow*SPAD + lcol)*2;

    for (int ch = 0; ch < 9; ch++) {
        __syncthreads();
        {   // load K,V chunk; both natural [kv][d], packed 8B stores
            int row = tid >> 1, dh = (tid & 1)*32;
            const float* ksrc = Y + ((size_t)(ns*576 + ch*64 + row))*1536 + 512 + h*64 + dh;
            #pragma unroll
            for (int j = 0; j < 8; j++) {
                float4 kv = *(const float4*)(ksrc + j*4);
                float kk[4] = {kv.x, kv.y, kv.z, kv.w};
                float4 vv4 = *(const float4*)(ksrc + 512 + j*4);
                float vvv[4] = {vv4.x, vv4.y, vv4.z, vv4.w};
                __nv_bfloat16 hh[4], ll[4];
                #pragma unroll
                for (int e = 0; e < 4; e++) split2(kk[e], hh[e], ll[e]);
                uint2 ukh = { packbf(hh[0],hh[1]), packbf(hh[2],hh[3]) };
                uint2 ukl = { packbf(ll[0],ll[1]), packbf(ll[2],ll[3]) };
                *(uint2*)(Kh + row*72 + dh + j*4) = ukh;
                *(uint2*)(Kl + row*72 + dh + j*4) = ukl;
                #pragma unroll
                for (int e = 0; e < 4; e++) split2(vvv[e], hh[e], ll[e]);
                uint2 uvh = { packbf(hh[0],hh[1]), packbf(hh[2],hh[3]) };
                uint2 uvl = { packbf(ll[0],ll[1]), packbf(ll[2],ll[3]) };
                *(uint2*)(Vh + row*72 + dh + j*4) = uvh;
                *(uint2*)(Vl + row*72 + dh + j*4) = uvl;
            }
        }
        __syncthreads();
        float sacc[8][4];
        #pragma unroll
        for (int t = 0; t < 8; t++)
            #pragma unroll
            for (int e = 0; e < 4; e++) sacc[t][e] = 0.f;
        #pragma unroll
        for (int k16 = 0; k16 < 4; k16++) {
            uint32_t kb = k16*32;
            uint32_t ah[4], al[4];
            ldm4(ah, uQh + kb);
            ldm4(al, uQl + kb);
            #pragma unroll
            for (int g = 0; g < 4; g++) {
                uint32_t kh[4], kl[4];
                ldm4(kh, uKh + g*16*SPAD*2 + kb);
                ldm4(kl, uKl + g*16*SPAD*2 + kb);
                mma16816(sacc[2*g],   ah, kh[0], kh[2]);
                mma16816(sacc[2*g],   al, kh[0], kh[2]);
                mma16816(sacc[2*g],   ah, kl[0], kl[2]);
                mma16816(sacc[2*g+1], ah, kh[1], kh[3]);
                mma16816(sacc[2*g+1], al, kh[1], kh[3]);
                mma16816(sacc[2*g+1], ah, kl[1], kl[3]);
            }
        }
        uint32_t phx[8][2], plx[8][2];
        #pragma unroll
        for (int hf = 0; hf < 2; hf++) {
            float mx = -1e30f;
            #pragma unroll
            for (int t = 0; t < 8; t++)
                mx = fmaxf(mx, fmaxf(sacc[t][2*hf], sacc[t][2*hf+1]));
            mx = fmaxf(mx, __shfl_xor_sync(0xffffffffu, mx, 1));
            mx = fmaxf(mx, __shfl_xor_sync(0xffffffffu, mx, 2));
            float nm = fmaxf(m[hf], mx);
            float alpha = __expf(m[hf] - nm);
            float rs = 0.f;
            #pragma unroll
            for (int t = 0; t < 8; t++) {
                float p0 = __expf(sacc[t][2*hf]   - nm);
                float p1 = __expf(sacc[t][2*hf+1] - nm);
                rs += p0 + p1;
                __nv_bfloat16 h0, l0, h1, l1;
                split2(p0, h0, l0); split2(p1, h1, l1);
                phx[t][hf] = packbf(h0, h1);
                plx[t][hf] = packbf(l0, l1);
            }
            rs += __shfl_xor_sync(0xffffffffu, rs, 1);
            rs += __shfl_xor_sync(0xffffffffu, rs, 2);
            l[hf] = l[hf]*alpha + rs;
            m[hf] = nm;
            #pragma unroll
            for (int t = 0; t < 8; t++) {
                oacc[t][2*hf]   *= alpha;
                oacc[t][2*hf+1] *= alpha;
            }
        }
        #pragma unroll
        for (int g = 0; g < 4; g++) {
            uint32_t pah[4] = {phx[2*g][0], phx[2*g][1], phx[2*g+1][0], phx[2*g+1][1]};
            uint32_t pal[4] = {plx[2*g][0], plx[2*g][1], plx[2*g+1][0], plx[2*g+1][1]};
            #pragma unroll
            for (int dt = 0; dt < 4; dt++) {
                uint32_t vh[4], vl[4];
                ldm4t(vh, uVh + g*16*SPAD*2 + dt*32);
                ldm4t(vl, uVl + g*16*SPAD*2 + dt*32);
                mma16816(oacc[2*dt],   pah, vh[0], vh[1]);
                mma16816(oacc[2*dt],   pal, vh[0], vh[1]);
                mma16816(oacc[2*dt],   pah, vl[0], vl[1]);
                mma16816(oacc[2*dt+1], pah, vh[2], vh[3]);
                mma16816(oacc[2*dt+1], pal, vh[2], vh[3]);
                mma16816(oacc[2*dt+1], pah, vl[2], vl[3]);
            }
        }
    }
    float inv0 = 1.f / l[0], inv1 = 1.f / l[1];
    int r0 = q0 + wid*16 + (lane >> 2);
    int col0 = h*64 + (lane & 3)*2;
    #pragma unroll
    for (int t = 0; t < 8; t++) {
        int col = col0 + t*8;
        __nv_bfloat16 h0, l0h, h1, l1h;
        split2(oacc[t][0]*inv0, h0, l0h);
        split2(oacc[t][1]*inv0, h1, l1h);
        size_t offA = ((size_t)(ns*576 + r0))*512 + col;
        *(__nv_bfloat162*)(Oh + offA) = __halves2bfloat162(h0, h1);
        *(__nv_bfloat162*)(Ol + offA) = __halves2bfloat162(l0h, l1h);
        split2(oacc[t][2]*inv1, h0, l0h);
        split2(oacc[t][3]*inv1, h1, l1h);
        size_t offB = ((size_t)(ns*576 + r0 + 8))*512 + col;
        *(__nv_bfloat162*)(Oh + offB) = __halves2bfloat162(h0, h1);
        *(__nv_bfloat162*)(Ol + offB) = __halves2bfloat162(l0h, l1h);
    }
}

// ---------------- temporal GN stats ----------------
__global__ void gn_stats_t() {
    int b = blockIdx.x, g = blockIdx.y, hw = blockIdx.z*64 + threadIdx.x;
    const float* base = g_x1 + ((size_t)b*512 + g*16)*9216 + hw;
    float s = 0.f, ss = 0.f;
    for (int cc = 0; cc < 16; cc++)
        #pragma unroll
        for (int t = 0; t < 16; t++) {
            float v = base[(size_t)cc*9216 + t*576];
            s += v; ss += v*v;
        }
    float mean = s*(1.f/256.f);
    float var  = ss*(1.f/256.f) - mean*mean;
    g_stt[((size_t)(b*576+hw)*32 + g)*2 + 0] = mean;
    g_stt[((size_t)(b*576+hw)*32 + g)*2 + 1] = rsqrtf(var + 1e-5f);
}

// --------- normalize + transpose temporal -> hi/lo bf16 token-major ---------
__global__ void norm_tr_t(const float* __restrict__ gw, const float* __restrict__ gb) {
    __shared__ float tile[32][33];
    int bt = blockIdx.x, b = bt >> 4, t = bt & 15;
    int hw0 = blockIdx.y*32, c0 = blockIdx.z*32;
    int tx = threadIdx.x, ty = threadIdx.y;
    #pragma unroll
    for (int i = 0; i < 4; i++) {
        int cl = ty + i*8, c = c0 + cl, hw = hw0 + tx;
        float mean = g_stt[((size_t)(b*576+hw)*32 + (c>>4))*2 + 0];
        float rstd = g_stt[((size_t)(b*576+hw)*32 + (c>>4))*2 + 1];
        float v = g_x1[(((size_t)b*512 + c)*16 + t)*576 + hw];
        tile[cl][tx] = (v - mean)*rstd*gw[c] + gb[c];
    }
    __syncthreads();
    #pragma unroll
    for (int i = 0; i < 4; i++) {
        int hwl = ty + i*8;
        size_t o = ((size_t)((b*576 + hw0 + hwl)*16 + t))*512 + c0 + tx;
        __nv_bfloat16 h, l; split2(tile[tx][hwl], h, l);
        g_Ah[o] = h; g_Al[o] = l;
    }
}

// ---------------- temporal attention ----------------
__global__ __launch_bounds__(256) void attn_temporal(const float* __restrict__ Y,
    const float* __restrict__ rpk, const float* __restrict__ rpv,
    __nv_bfloat16* __restrict__ Oh, __nv_bfloat16* __restrict__ Ol) {
    __shared__ float qs[16][68], ks[16][68], vs[16][68];
    __shared__ float pk[33][68], pvt[33][68], wsm[16][20];
    int h = blockIdx.x, samp = blockIdx.y, tid = threadIdx.x;
    for (int i = tid; i < 33*64; i += 256) {
        pk [i>>6][i&63] = rpk[i];
        pvt[i>>6][i&63] = rpv[i];
    }
    {
        int t = tid >> 4, d0 = (tid & 15)*4;
        const float* base = Y + ((size_t)(samp*16 + t))*1536 + h*64 + d0;
        float4 q4 = *(const float4*)(base);
        float4 k4 = *(const float4*)(base + 512);
        float4 v4 = *(const float4*)(base + 1024);
        qs[t][d0+0]=q4.x; qs[t][d0+1]=q4.y; qs[t][d0+2]=q4.z; qs[t][d0+3]=q4.w;
        ks[t][d0+0]=k4.x; ks[t][d0+1]=k4.y; ks[t][d0+2]=k4.z; ks[t][d0+3]=k4.w;
        vs[t][d0+0]=v4.x; vs[t][d0+1]=v4.y; vs[t][d0+2]=v4.z; vs[t][d0+3]=v4.w;
    }
    __syncthreads();
    {
        int t = tid >> 4, s = tid & 15;
        float wv = -1e30f;
        if (s <= t) {
            float a = 0.f, bb = 0.f;
            int ri = t - s + 16;
            for (int d = 0; d < 64; d++) {
                a  += qs[t][d]*ks[s][d];
                bb += qs[s][d]*pk[ri][d];
            }
            wv = 0.125f*a + SCALE*bb;
        }
        float mx = wv;
        #pragma unroll
        for (int o = 8; o; o >>= 1) mx = fmaxf(mx, __shfl_xor_sync(0xffffffffu, mx, o, 16));
        float e = (s <= t) ? __expf(wv - mx) : 0.f;
        float sum = e;
        #pragma unroll
        for (int o = 8; o; o >>= 1) sum += __shfl_xor_sync(0xffffffffu, sum, o, 16);
        wsm[t][s] = e / sum;
    }
    __syncthreads();
    {
        int t = tid >> 4, d0 = (tid & 15)*4;
        float o0 = 0.f, o1 = 0.f, o2 = 0.f, o3 = 0.f;
        #pragma unroll
        for (int s = 0; s < 16; s++) {
            float p = wsm[t][s];
            int ri = s - t + 16;
            o0 += p*(vs[s][d0+0] + pvt[ri][d0+0]);
            o1 += p*(vs[s][d0+1] + pvt[ri][d0+1]);
            o2 += p*(vs[s][d0+2] + pvt[ri][d0+2]);
            o3 += p*(vs[s][d0+3] + pvt[ri][d0+3]);
        }
        size_t off = ((size_t)(samp*16 + t))*512 + h*64 + d0;
        __nv_bfloat16 h0, l0, h1, l1, h2, l2, h3, l3;
        split2(o0, h0, l0); split2(o1, h1, l1);
        split2(o2, h2, l2); split2(o3, h3, l3);
        *(__nv_bfloat162*)(Oh + off)     = __halves2bfloat162(h0, h1);
        *(__nv_bfloat162*)(Oh + off + 2) = __halves2bfloat162(h2, h3);
        *(__nv_bfloat162*)(Ol + off)     = __halves2bfloat162(l0, l1);
        *(__nv_bfloat162*)(Ol + off + 2) = __halves2bfloat162(l2, l3);
    }
}

extern "C" void kernel_launch(void* const* d_in, const int* in_sizes, int n_in,
                              void* d_out, int out_size) {
    const float* x        = (const float*)d_in[0];
    const float* norm_s_w = (const float*)d_in[1];
    const float* norm_s_b = (const float*)d_in[2];
    const float* qkv_s_w  = (const float*)d_in[3];
    const float* qkv_s_b  = (const float*)d_in[4];
    const float* proj_s_w = (const float*)d_in[5];
    const float* proj_s_b = (const float*)d_in[6];
    const float* norm_t_w = (const float*)d_in[7];
    const float* norm_t_b = (const float*)d_in[8];
    const float* qkv_t_w  = (const float*)d_in[9];
    const float* qkv_t_b  = (const float*)d_in[10];
    const float* proj_t_w = (const float*)d_in[11];
    const float* proj_t_b = (const float*)d_in[12];
    const float* rpk      = (const float*)d_in[13];
    const float* rpv      = (const float*)d_in[14];
    float* out = (float*)d_out;

    float *gY, *gX1;
    __nv_bfloat16 *gAh, *gAl, *gWh, *gWl;
    cudaGetSymbolAddress((void**)&gY,  g_Y);
    cudaGetSymbolAddress((void**)&gX1, g_x1);
    cudaGetSymbolAddress((void**)&gAh, g_Ah);
    cudaGetSymbolAddress((void**)&gAl, g_Al);
    cudaGetSymbolAddress((void**)&gWh, g_Wh);
    cudaGetSymbolAddress((void**)&gWl, g_Wl);

    cudaFuncSetAttribute(gemm_mma, cudaFuncAttributeMaxDynamicSharedMemorySize, GEMM_SMEM);
    cudaFuncSetAttribute(gemm_proj_resid, cudaFuncAttributeMaxDynamicSharedMemorySize, GEMM_SMEM);
    cudaFuncSetAttribute(gemm_proj_resid_t, cudaFuncAttributeMaxDynamicSharedMemorySize, GEMM_SMEM);
    cudaFuncSetAttribute(attn_spatial_mma, cudaFuncAttributeMaxDynamicSharedMemorySize, AT_SMEM);

    dim3 tb(32, 8);
    dim3 tg(32, 18, 16);

    // spatial branch
    gn_stats_s<<<dim3(32,32), 256>>>(x);
    norm_tr_s<<<tg, tb>>>(x, norm_s_w, norm_s_b);
    wsplit2<<<3072, 256>>>(qkv_s_w, proj_s_w);
    gemm_mma<<<dim3(12,144), 256, GEMM_SMEM>>>(gAh, gAl, gWh, gWl, qkv_s_b, gY, 1536);
    attn_spatial_mma<<<dim3(9,8,32), 128, AT_SMEM>>>(gY, gAh, gAl);
    gemm_proj_resid<<<dim3(4,144), 256, GEMM_SMEM>>>(gAh, gAl, gWh + WOFF, gWl + WOFF,
                                                     proj_s_b, x, gX1);
    // temporal branch
    gn_stats_t<<<dim3(2,32,9), 64>>>();
    norm_tr_t<<<tg, tb>>>(norm_t_w, norm_t_b);
    wsplit2<<<3072, 256>>>(qkv_t_w, proj_t_w);
    gemm_mma<<<dim3(12,144), 256, GEMM_SMEM>>>(gAh, gAl, gWh, gWl, qkv_t_b, gY, 1536);
    attn_temporal<<<dim3(8,1152), 256>>>(gY, rpk, rpv, gAh, gAl);
    gemm_proj_resid_t<<<dim3(4,144), 256, GEMM_SMEM>>>(gAh, gAl, gWh + WOFF, gWl + WOFF,
                                                       proj_t_b, gX1, out);
}